// round 6
// baseline (speedup 1.0000x reference)
#include <cuda_runtime.h>
#include <cuda_bf16.h>
#include <math.h>
#include <stdint.h>

#define NN 16384
#define NE 32
#define NH 256
#define OUTD 5

typedef __nv_bfloat16 bf16;

// ---------------- scratch (device globals) ----------------
__device__ __align__(16) float g_cvec[256];
__device__ __align__(16) float g_V[NN * NH];
__device__ __align__(16) float g_z[NN * NH];

__device__ __align__(16) bf16 g_Mt_hi[256 * 256], g_Mt_lo[256 * 256];
__device__ __align__(16) bf16 g_in1_hi[NN * 512], g_in1_lo[NN * 512];  // [th || Hagg]
__device__ __align__(16) bf16 g_cat_hi[NN * 512], g_cat_lo[NN * 512];  // [x_e || H_e]
__device__ __align__(16) bf16 g_prev_hi[NN * 256], g_prev_lo[NN * 256];
__device__ __align__(16) bf16 g_rh_hi[NN * 256],  g_rh_lo[NN * 256];
__device__ __align__(16) bf16 g_Whe_hi[256 * 512], g_Whe_lo[256 * 512];
__device__ __align__(16) bf16 g_Uzr_hi[512 * 768], g_Uzr_lo[512 * 768];
__device__ __align__(16) bf16 g_Un_hi[256 * 768],  g_Un_lo[256 * 768];

// ---------------- PTX helpers ----------------
__device__ __forceinline__ uint32_t smem_u32(const void* p) {
    uint32_t a;
    asm("{ .reg .u64 t; cvta.to.shared.u64 t, %1; cvt.u32.u64 %0, t; }" : "=r"(a) : "l"(p));
    return a;
}
__device__ __forceinline__ void cp_async16(uint32_t s, const void* g) {
    asm volatile("cp.async.cg.shared.global [%0], [%1], 16;" :: "r"(s), "l"(g) : "memory");
}
__device__ __forceinline__ void cp_commit() {
    asm volatile("cp.async.commit_group;" ::: "memory");
}
__device__ __forceinline__ void ldmx4(uint32_t* r, uint32_t addr) {
    asm volatile("ldmatrix.sync.aligned.m8n8.x4.shared.b16 {%0,%1,%2,%3}, [%4];"
                 : "=r"(r[0]), "=r"(r[1]), "=r"(r[2]), "=r"(r[3]) : "r"(addr));
}
__device__ __forceinline__ void mma16816(float* c, const uint32_t* a, uint32_t b0, uint32_t b1) {
    asm volatile(
        "mma.sync.aligned.m16n8k16.row.col.f32.bf16.bf16.f32 "
        "{%0,%1,%2,%3}, {%4,%5,%6,%7}, {%8,%9}, {%0,%1,%2,%3};"
        : "+f"(c[0]), "+f"(c[1]), "+f"(c[2]), "+f"(c[3])
        : "r"(a[0]), "r"(a[1]), "r"(a[2]), "r"(a[3]), "r"(b0), "r"(b1));
}
__device__ __forceinline__ void split_write(bf16* hi, bf16* lo, size_t off, float x) {
    bf16 h = __float2bfloat16_rn(x);
    hi[off] = h;
    lo[off] = __float2bfloat16_rn(x - __bfloat162float(h));
}

// ---------------- bf16 double-split GEMM: BM=128, BN=256, BK=32 ----------------
// 512 threads = 16 warps (2 M x 8 N), warp tile 64x32. 3-stage cp.async pipeline.
// Stage layout (pitch 80B): A-hi[128] | A-lo[128] | W-hi[256] | W-lo[256]
// OUTMODE: 2 = relu+bf16 split; 3 = zr epilogue; 4 = n/final epilogue; 5 = fp32+bias.
#define ST 61440
#define MMG_SMEM (3 * ST)

template <int OUTMODE>
__global__ void __launch_bounds__(512, 1) mma3(
    const bf16* __restrict__ A1h, const bf16* __restrict__ A1l, int lda1,
    const bf16* __restrict__ A2h, const bf16* __restrict__ A2l, int lda2, int splitK,
    const bf16* __restrict__ Wh, const bf16* __restrict__ Wl, int ldw, int K,
    bf16* __restrict__ Chi, bf16* __restrict__ Clo, int ldc, int coff,
    const float* __restrict__ bg, const float* __restrict__ prevp,
    float* __restrict__ zbuf,
    bf16* __restrict__ rhhi, bf16* __restrict__ rhlo,
    float* __restrict__ outh)
{
    extern __shared__ char sm[];
    const uint32_t base = smem_u32(sm);
    const int t = threadIdx.x, wid = t >> 5, lane = t & 31;
    const int wm = wid & 1, wn = wid >> 1;           // 2 x 8 warps
    const int row0 = blockIdx.y * 128, col0 = blockIdx.x * 256;
    const int chunks = K >> 5;

    auto load_stage = [&](int s, int ck) {
        int k0 = ck * 32;
        const bf16 *ah, *al;
        int lda, kk;
        if (k0 < splitK) { ah = A1h; al = A1l; lda = lda1; kk = k0; }
        else             { ah = A2h; al = A2l; lda = lda2; kk = k0 - splitK; }
        uint32_t sb = base + (uint32_t)s * ST;
        {   // A tiles: 128 rows x 4 16B-chunks = 512 loads each
            int r = t >> 2, c = t & 3;
            uint32_t so = r * 80 + c * 16;
            const bf16* gh = ah + (size_t)(row0 + r) * lda + kk + c * 8;
            const bf16* gl = al + (size_t)(row0 + r) * lda + kk + c * 8;
            cp_async16(sb + so, gh);
            cp_async16(sb + 10240 + so, gl);
        }
#pragma unroll
        for (int i = 0; i < 2; i++) {   // W tiles: 256 rows x 4 chunks = 1024 loads each
            int idx = t + i * 512;
            int r = idx >> 2, c = idx & 3;
            uint32_t so = r * 80 + c * 16;
            cp_async16(sb + 20480 + so, Wh + (size_t)(col0 + r) * ldw + k0 + c * 8);
            cp_async16(sb + 40960 + so, Wl + (size_t)(col0 + r) * ldw + k0 + c * 8);
        }
        cp_commit();
    };

    float acc[4][4][4];
#pragma unroll
    for (int a = 0; a < 4; a++)
#pragma unroll
        for (int b = 0; b < 4; b++)
#pragma unroll
            for (int c = 0; c < 4; c++) acc[a][b][c] = 0.f;

    load_stage(0, 0);
    if (chunks > 1) load_stage(1, 1);

    for (int i = 0; i < chunks; i++) {
        uint32_t sb = base + (uint32_t)(i % 3) * ST;
        if (i + 2 < chunks) {
            load_stage((i + 2) % 3, i + 2);
            asm volatile("cp.async.wait_group 2;" ::: "memory");
        } else if (i + 1 < chunks) {
            asm volatile("cp.async.wait_group 1;" ::: "memory");
        } else {
            asm volatile("cp.async.wait_group 0;" ::: "memory");
        }
        __syncthreads();

#pragma unroll
        for (int ks = 0; ks < 2; ks++) {
            int kb = ks * 16;
            uint32_t ra[4][4], rbh[2][4], rbl[2][4];
            int arow[4];
            int akc = (kb >> 3) + (lane >> 4);
#pragma unroll
            for (int im = 0; im < 4; im++) {
                arow[im] = wm * 64 + im * 16 + (lane & 15);
                ldmx4(ra[im], sb + arow[im] * 80 + akc * 16);
            }
#pragma unroll
            for (int ib = 0; ib < 2; ib++) {
                int n = wn * 32 + ib * 16 + ((lane & 16) ? 8 : 0) + (lane & 7);
                int kc = (kb >> 3) + ((lane >> 3) & 1);
                ldmx4(rbh[ib], sb + 20480 + n * 80 + kc * 16);
                ldmx4(rbl[ib], sb + 40960 + n * 80 + kc * 16);
            }
#pragma unroll
            for (int im = 0; im < 4; im++)
#pragma unroll
                for (int in = 0; in < 4; in++)
                    mma16816(acc[im][in], ra[im], rbh[in >> 1][(in & 1) * 2], rbh[in >> 1][(in & 1) * 2 + 1]);
#pragma unroll
            for (int im = 0; im < 4; im++)
#pragma unroll
                for (int in = 0; in < 4; in++)
                    mma16816(acc[im][in], ra[im], rbl[in >> 1][(in & 1) * 2], rbl[in >> 1][(in & 1) * 2 + 1]);
#pragma unroll
            for (int im = 0; im < 4; im++)
                ldmx4(ra[im], sb + 10240 + arow[im] * 80 + akc * 16);
#pragma unroll
            for (int im = 0; im < 4; im++)
#pragma unroll
                for (int in = 0; in < 4; in++)
                    mma16816(acc[im][in], ra[im], rbh[in >> 1][(in & 1) * 2], rbh[in >> 1][(in & 1) * 2 + 1]);
        }
        __syncthreads();
    }

    // ---------------- epilogue ----------------
    auto emit = [&](int mm, int cc, float v) {
        if (OUTMODE == 2) {
            split_write(Chi, Clo, (size_t)mm * ldc + coff + cc, fmaxf(v, 0.f));
        } else if (OUTMODE == 3) {
            float s = 1.f / (1.f + expf(-(v + bg[cc])));
            if (cc < 256) {
                zbuf[(size_t)mm * 256 + cc] = s;
            } else {
                int j = cc - 256;
                float rh = s * prevp[(size_t)mm * 256 + j];
                split_write(rhhi, rhlo, (size_t)mm * 256 + j, rh);
            }
        } else if (OUTMODE == 4) {
            float nv = fmaxf(v + bg[512 + cc], 0.f);
            float z = zbuf[(size_t)mm * 256 + cc];
            float pv = prevp[(size_t)mm * 256 + cc];
            outh[(size_t)mm * 256 + cc] = (1.f - z) * nv + z * pv;
        } else {  // 5: fp32 + bias
            outh[(size_t)mm * 256 + cc] = v + bg[cc];
        }
    };
#pragma unroll
    for (int im = 0; im < 4; im++) {
#pragma unroll
        for (int in = 0; in < 4; in++) {
            int m = row0 + wm * 64 + im * 16 + (lane >> 2);
            int c = col0 + wn * 32 + in * 8 + (lane & 3) * 2;
            emit(m, c, acc[im][in][0]);
            emit(m, c + 1, acc[im][in][1]);
            emit(m + 8, c, acc[im][in][2]);
            emit(m + 8, c + 1, acc[im][in][3]);
        }
    }
}

// ---------------- Mt = (Wt^T @ Ws)^T split, cvec = bt @ Ws ----------------
__global__ void computeM(const float* __restrict__ Wt, const float* __restrict__ Ws,
                         const float* __restrict__ bt,
                         bf16* __restrict__ MtH, bf16* __restrict__ MtL,
                         float* __restrict__ cvec)
{
    int k = blockIdx.x, j = threadIdx.x;
    float s = 0.f;
#pragma unroll 8
    for (int a = 0; a < 64; a++) s = fmaf(Wt[a * 256 + k], Ws[a * 256 + j], s);
    split_write(MtH, MtL, (size_t)j * 256 + k, s);
    if (k == 0) {
        float c = 0.f;
#pragma unroll 8
        for (int a = 0; a < 64; a++) c = fmaf(bt[a], Ws[a * 256 + j], c);
        cvec[j] = c;
    }
}

// ---------------- attention (writes in1 cols 256:512) ----------------
__global__ void __launch_bounds__(256) attn_kernel(
    const float* __restrict__ spat, const float* __restrict__ V,
    bf16* __restrict__ hi, bf16* __restrict__ lo)
{
    __shared__ float sp[NE * NH];
    __shared__ float vs[NH];
    __shared__ float attn_s[NE];
    __shared__ float ws[NE];

    int n = blockIdx.x;
    int t = threadIdx.x;

    vs[t] = V[(size_t)n * NH + t];
    const float4* g = (const float4*)(spat + (size_t)n * NE * NH);
    float4* s4 = (float4*)sp;
#pragma unroll
    for (int i = 0; i < 8; i++) s4[t + i * 256] = g[t + i * 256];
    __syncthreads();

    int warp = t >> 5, lane = t & 31;
#pragma unroll
    for (int ei = 0; ei < 4; ei++) {
        int e = warp * 4 + ei;
        float s = 0.f;
#pragma unroll
        for (int i = 0; i < 8; i++)
            s = fmaf(sp[e * NH + lane + i * 32], vs[lane + i * 32], s);
#pragma unroll
        for (int o = 16; o; o >>= 1) s += __shfl_xor_sync(0xffffffffu, s, o);
        if (lane == 0) attn_s[e] = s * 4.0f;
    }
    __syncthreads();

    if (t < 32) {
        float a = attn_s[t];
        float m = a;
#pragma unroll
        for (int o = 16; o; o >>= 1) m = fmaxf(m, __shfl_xor_sync(0xffffffffu, m, o));
        float p = expf(a - m);
        float ssum = p;
#pragma unroll
        for (int o = 16; o; o >>= 1) ssum += __shfl_xor_sync(0xffffffffu, ssum, o);
        ws[t] = p / ssum;
    }
    __syncthreads();

    float acc = 0.f;
#pragma unroll
    for (int e = 0; e < NE; e++) acc = fmaf(ws[e], sp[e * NH + t], acc);
    split_write(hi, lo, (size_t)n * 512 + 256 + t, acc);
}

// ---------------- fused prep: prev split, th split, x_e ----------------
__global__ void __launch_bounds__(256) prep_kernel(
    const float* __restrict__ prev, const float* __restrict__ th,
    const float* __restrict__ xy, const float* __restrict__ Wxy,
    bf16* __restrict__ ph, bf16* __restrict__ pl,
    bf16* __restrict__ i1h, bf16* __restrict__ i1l,
    bf16* __restrict__ ch, bf16* __restrict__ cl)
{
    int n = blockIdx.x, c = threadIdx.x;
    size_t i = (size_t)n * 256 + c;
    split_write(ph, pl, i, prev[i]);
    split_write(i1h, i1l, (size_t)n * 512 + c, th[i]);
    float x0 = xy[n * 2 + 0], x1 = xy[n * 2 + 1];
    float2 w = *(const float2*)&Wxy[c * 2];
    float v = fmaxf(fmaf(x0, w.x, x1 * w.y), 0.f);
    split_write(ch, cl, (size_t)n * 512 + c, v);
}

// ---------------- weight merge + split ----------------
__global__ void merge_weights(
    const float* __restrict__ Whe, const float* __restrict__ Wih, const float* __restrict__ Whh,
    bf16* __restrict__ WheH, bf16* __restrict__ WheL,
    bf16* __restrict__ UzrH, bf16* __restrict__ UzrL,
    bf16* __restrict__ UnH,  bf16* __restrict__ UnL)
{
    int i = blockIdx.x * 256 + threadIdx.x;
    float x;
    if (i < 131072) {
        x = Whe[i];
        split_write(WheH, WheL, i, x);
    } else if (i < 131072 + 393216) {
        int q = i - 131072;
        int j = q / 768, k = q - j * 768;
        int g = j >> 8, r = j & 255;
        x = (k < 512) ? Wih[g * 131072 + r * 512 + k] : Whh[g * 65536 + r * 256 + (k - 512)];
        split_write(UzrH, UzrL, q, x);
    } else {
        int q = i - 524288;
        int j = q / 768, k = q - j * 768;
        x = (k < 512) ? Wih[262144 + j * 512 + k] : Whh[131072 + j * 256 + (k - 512)];
        split_write(UnH, UnL, q, x);
    }
}

// ---------------- predict head ----------------
__global__ void __launch_bounds__(256) predict_kernel(
    const float* __restrict__ hid, const float* __restrict__ Wp,
    const float* __restrict__ bp, float* __restrict__ out)
{
    __shared__ float hs[NH];
    int n = blockIdx.x, t = threadIdx.x;
    hs[t] = hid[(size_t)n * NH + t];
    __syncthreads();
    int w = t >> 5, lane = t & 31;
    if (w < OUTD) {
        float s = 0.f;
#pragma unroll
        for (int i = 0; i < 8; i++)
            s = fmaf(hs[lane + i * 32], Wp[w * NH + lane + i * 32], s);
#pragma unroll
        for (int o = 16; o; o >>= 1) s += __shfl_xor_sync(0xffffffffu, s, o);
        if (lane == 0) out[(size_t)n * OUTD + w] = s + bp[w];
    }
}

// ---------------- host launcher ----------------
extern "C" void kernel_launch(void* const* d_in, const int* in_sizes, int n_in,
                              void* d_out, int out_size)
{
    const float* xy   = (const float*)d_in[0];
    const float* th   = (const float*)d_in[1];
    const float* spat = (const float*)d_in[2];
    const float* prev = (const float*)d_in[3];
    const float* Wt   = (const float*)d_in[4];
    const float* bt   = (const float*)d_in[5];
    const float* Ws   = (const float*)d_in[6];
    // d_in[7] = bs: softmax-invariant, dropped.
    const float* Wxy  = (const float*)d_in[8];
    const float* Whe  = (const float*)d_in[9];
    const float* Wih  = (const float*)d_in[10];
    const float* Whh  = (const float*)d_in[11];
    const float* bg   = (const float*)d_in[12];
    const float* Wp   = (const float*)d_in[13];
    const float* bp   = (const float*)d_in[14];

    float* out_pred   = (float*)d_out;
    float* out_hidden = (float*)d_out + NN * OUTD;

    float *pCvec, *pV, *pZ;
    bf16 *pMth, *pMtl, *pIn1h, *pIn1l, *pCath, *pCatl, *pPrevh, *pPrevl, *pRhh, *pRhl;
    bf16 *pWheh, *pWhel, *pUzrh, *pUzrl, *pUnh, *pUnl;
    cudaGetSymbolAddress((void**)&pCvec, g_cvec);
    cudaGetSymbolAddress((void**)&pV, g_V);
    cudaGetSymbolAddress((void**)&pZ, g_z);
    cudaGetSymbolAddress((void**)&pMth, g_Mt_hi);
    cudaGetSymbolAddress((void**)&pMtl, g_Mt_lo);
    cudaGetSymbolAddress((void**)&pIn1h, g_in1_hi);
    cudaGetSymbolAddress((void**)&pIn1l, g_in1_lo);
    cudaGetSymbolAddress((void**)&pCath, g_cat_hi);
    cudaGetSymbolAddress((void**)&pCatl, g_cat_lo);
    cudaGetSymbolAddress((void**)&pPrevh, g_prev_hi);
    cudaGetSymbolAddress((void**)&pPrevl, g_prev_lo);
    cudaGetSymbolAddress((void**)&pRhh, g_rh_hi);
    cudaGetSymbolAddress((void**)&pRhl, g_rh_lo);
    cudaGetSymbolAddress((void**)&pWheh, g_Whe_hi);
    cudaGetSymbolAddress((void**)&pWhel, g_Whe_lo);
    cudaGetSymbolAddress((void**)&pUzrh, g_Uzr_hi);
    cudaGetSymbolAddress((void**)&pUzrl, g_Uzr_lo);
    cudaGetSymbolAddress((void**)&pUnh, g_Un_hi);
    cudaGetSymbolAddress((void**)&pUnl, g_Un_lo);

    cudaFuncSetAttribute(mma3<2>, cudaFuncAttributeMaxDynamicSharedMemorySize, MMG_SMEM);
    cudaFuncSetAttribute(mma3<3>, cudaFuncAttributeMaxDynamicSharedMemorySize, MMG_SMEM);
    cudaFuncSetAttribute(mma3<4>, cudaFuncAttributeMaxDynamicSharedMemorySize, MMG_SMEM);
    cudaFuncSetAttribute(mma3<5>, cudaFuncAttributeMaxDynamicSharedMemorySize, MMG_SMEM);

    dim3 blk(256);
    dim3 gblk(512);
    const int MB = NN / 128;

    // prep
    merge_weights<<<2816, blk>>>(Whe, Wih, Whh, pWheh, pWhel, pUzrh, pUzrl, pUnh, pUnl);
    computeM<<<256, blk>>>(Wt, Ws, bt, pMth, pMtl, pCvec);
    prep_kernel<<<NN, blk>>>(prev, th, xy, Wxy, pPrevh, pPrevl, pIn1h, pIn1l, pCath, pCatl);

    // V = th @ Mt^T + cvec (N=256 -> 1 col block)
    mma3<5><<<dim3(1, MB), gblk, MMG_SMEM>>>(
        pIn1h, pIn1l, 512, pIn1h, pIn1l, 512, 1024,
        pMth, pMtl, 256, 256,
        nullptr, nullptr, 0, 0, pCvec, nullptr, nullptr, nullptr, nullptr, pV);

    // attention -> Hagg (in1 cols 256:512)
    attn_kernel<<<NN, blk>>>(spat, pV, pIn1h, pIn1l);

    // H_e = relu(in1 @ Whe^T) -> cat[:,256:512]
    mma3<2><<<dim3(1, MB), gblk, MMG_SMEM>>>(
        pIn1h, pIn1l, 512, pIn1h, pIn1l, 512, 512,
        pWheh, pWhel, 512, 512,
        pCath, pCatl, 512, 256, nullptr, nullptr, nullptr, nullptr, nullptr, nullptr);

    // z,r = sigmoid([cat||prev] @ Uzr^T + bg); writes g_z and rh=r*prev (N=512 -> 2 blocks)
    mma3<3><<<dim3(2, MB), gblk, MMG_SMEM>>>(
        pCath, pCatl, 512, pPrevh, pPrevl, 256, 512,
        pUzrh, pUzrl, 768, 768,
        nullptr, nullptr, 0, 0, bg, prev, pZ, pRhh, pRhl, nullptr);

    // n = relu([cat||rh] @ Un^T + bg); hidden -> out_hidden
    mma3<4><<<dim3(1, MB), gblk, MMG_SMEM>>>(
        pCath, pCatl, 512, pRhh, pRhl, 256, 512,
        pUnh, pUnl, 768, 768,
        nullptr, nullptr, 0, 0, bg, prev, pZ, nullptr, nullptr, out_hidden);

    // predict head
    predict_kernel<<<NN, blk>>>(out_hidden, Wp, bp, out_pred);
}

// round 7
// speedup vs baseline: 1.1989x; 1.1989x over previous
#include <cuda_runtime.h>
#include <cuda_fp16.h>
#include <math.h>
#include <stdint.h>

#define NN 16384
#define NE 32
#define NH 256
#define OUTD 5

typedef __half fp16;

// ---------------- scratch (device globals) ----------------
__device__ __align__(16) float g_cvec[256];
__device__ __align__(16) float g_V[NN * NH];
__device__ __align__(16) float g_z[NN * NH];

__device__ __align__(16) fp16 g_Mt_hi[256 * 256], g_Mt_lo[256 * 256];
__device__ __align__(16) fp16 g_in1_hi[NN * 512], g_in1_lo[NN * 512];  // [th || Hagg]
__device__ __align__(16) fp16 g_cat_hi[NN * 512], g_cat_lo[NN * 512];  // [x_e || H_e]
__device__ __align__(16) fp16 g_prev_hi[NN * 256], g_prev_lo[NN * 256];
__device__ __align__(16) fp16 g_rh_hi[NN * 256],  g_rh_lo[NN * 256];
__device__ __align__(16) fp16 g_Whe_hi[256 * 512], g_Whe_lo[256 * 512];
__device__ __align__(16) fp16 g_Uzr[512 * 768];   // single fp16 (2-term GEMM)
__device__ __align__(16) fp16 g_Un[256 * 768];    // single fp16 (2-term GEMM)

// ---------------- PTX helpers ----------------
__device__ __forceinline__ uint32_t smem_u32(const void* p) {
    uint32_t a;
    asm("{ .reg .u64 t; cvta.to.shared.u64 t, %1; cvt.u32.u64 %0, t; }" : "=r"(a) : "l"(p));
    return a;
}
__device__ __forceinline__ void cp_async16(uint32_t s, const void* g) {
    asm volatile("cp.async.cg.shared.global [%0], [%1], 16;" :: "r"(s), "l"(g) : "memory");
}
__device__ __forceinline__ void cp_commit() {
    asm volatile("cp.async.commit_group;" ::: "memory");
}
__device__ __forceinline__ void ldmx4(uint32_t* r, uint32_t addr) {
    asm volatile("ldmatrix.sync.aligned.m8n8.x4.shared.b16 {%0,%1,%2,%3}, [%4];"
                 : "=r"(r[0]), "=r"(r[1]), "=r"(r[2]), "=r"(r[3]) : "r"(addr));
}
__device__ __forceinline__ void mma16816(float* c, const uint32_t* a, uint32_t b0, uint32_t b1) {
    asm volatile(
        "mma.sync.aligned.m16n8k16.row.col.f32.f16.f16.f32 "
        "{%0,%1,%2,%3}, {%4,%5,%6,%7}, {%8,%9}, {%0,%1,%2,%3};"
        : "+f"(c[0]), "+f"(c[1]), "+f"(c[2]), "+f"(c[3])
        : "r"(a[0]), "r"(a[1]), "r"(a[2]), "r"(a[3]), "r"(b0), "r"(b1));
}
__device__ __forceinline__ void split_write(fp16* hi, fp16* lo, size_t off, float x) {
    fp16 h = __float2half_rn(x);
    hi[off] = h;
    lo[off] = __float2half_rn(x - __half2float(h));
}

// ---------------- fp16 split GEMM: BM=BN=128, BK=32, 256 thr, 2-stage, 2 CTA/SM ----
// NTERMS=3: A(hi,lo), W(hi,lo): hi*hi + hi*lo + lo*hi  (error ~u^2)
// NTERMS=2: A(hi,lo), W single: hi*W + lo*W            (error ~u on W, backward-stable)
// OUTMODE: 2 = relu+fp16 split; 3 = zr epilogue; 4 = n/final epilogue; 5 = fp32+bias.
template <int OUTMODE, int NTERMS>
__global__ void __launch_bounds__(256, 2) mma3(
    const fp16* __restrict__ A1h, const fp16* __restrict__ A1l, int lda1,
    const fp16* __restrict__ A2h, const fp16* __restrict__ A2l, int lda2, int splitK,
    const fp16* __restrict__ Wh, const fp16* __restrict__ Wl, int ldw, int K,
    fp16* __restrict__ Chi, fp16* __restrict__ Clo, int ldc, int coff,
    const float* __restrict__ bg, const float* __restrict__ prevp,
    float* __restrict__ zbuf,
    fp16* __restrict__ rhhi, fp16* __restrict__ rhlo,
    float* __restrict__ outh)
{
    constexpr uint32_t ST = (NTERMS == 3) ? 40960u : 30720u;
    extern __shared__ char sm[];
    const uint32_t base = smem_u32(sm);
    const int t = threadIdx.x, wid = t >> 5, lane = t & 31;
    const int wm = wid & 1, wn = wid >> 1;
    const int row0 = blockIdx.y * 128, col0 = blockIdx.x * 128;
    const int chunks = K >> 5;

    auto load_stage = [&](int s, int ck) {
        int k0 = ck * 32;
        const fp16 *ah, *al;
        int lda, kk;
        if (k0 < splitK) { ah = A1h; al = A1l; lda = lda1; kk = k0; }
        else             { ah = A2h; al = A2l; lda = lda2; kk = k0 - splitK; }
        uint32_t sb = base + (uint32_t)s * ST;
#pragma unroll
        for (int half = 0; half < 2; half++) {
            int idx = t + half * 256;
            int r = idx >> 2, c = idx & 3;
            uint32_t so = r * 80 + c * 16;
            cp_async16(sb + so,          ah + (size_t)(row0 + r) * lda + kk + c * 8);
            cp_async16(sb + 10240 + so,  al + (size_t)(row0 + r) * lda + kk + c * 8);
            cp_async16(sb + 20480 + so,  Wh + (size_t)(col0 + r) * ldw + k0 + c * 8);
            if (NTERMS == 3)
                cp_async16(sb + 30720 + so, Wl + (size_t)(col0 + r) * ldw + k0 + c * 8);
        }
        cp_commit();
    };

    float acc[4][4][4];
#pragma unroll
    for (int a = 0; a < 4; a++)
#pragma unroll
        for (int b = 0; b < 4; b++)
#pragma unroll
            for (int c = 0; c < 4; c++) acc[a][b][c] = 0.f;

    load_stage(0, 0);
    if (chunks > 1) load_stage(1, 1);

    for (int i = 0; i < chunks; i++) {
        uint32_t sb = base + (uint32_t)(i & 1) * ST;
        if (i + 1 < chunks) asm volatile("cp.async.wait_group 1;" ::: "memory");
        else                asm volatile("cp.async.wait_group 0;" ::: "memory");
        __syncthreads();

#pragma unroll
        for (int ks = 0; ks < 2; ks++) {
            int kb = ks * 16;
            int arow[4];
            int akc = (kb >> 3) + (lane >> 4);
            uint32_t ra[4][4], rbh[2][4];
#pragma unroll
            for (int im = 0; im < 4; im++) {
                arow[im] = wm * 64 + im * 16 + (lane & 15);
                ldmx4(ra[im], sb + arow[im] * 80 + akc * 16);
            }
#pragma unroll
            for (int ib = 0; ib < 2; ib++) {
                int n = wn * 32 + ib * 16 + ((lane & 16) ? 8 : 0) + (lane & 7);
                int kc = (kb >> 3) + ((lane >> 3) & 1);
                ldmx4(rbh[ib], sb + 20480 + n * 80 + kc * 16);
            }
            // A-hi * W-hi
#pragma unroll
            for (int im = 0; im < 4; im++)
#pragma unroll
                for (int in = 0; in < 4; in++)
                    mma16816(acc[im][in], ra[im], rbh[in >> 1][(in & 1) * 2], rbh[in >> 1][(in & 1) * 2 + 1]);
            if (NTERMS == 3) {
                uint32_t rbl[2][4];
#pragma unroll
                for (int ib = 0; ib < 2; ib++) {
                    int n = wn * 32 + ib * 16 + ((lane & 16) ? 8 : 0) + (lane & 7);
                    int kc = (kb >> 3) + ((lane >> 3) & 1);
                    ldmx4(rbl[ib], sb + 30720 + n * 80 + kc * 16);
                }
                // A-hi * W-lo
#pragma unroll
                for (int im = 0; im < 4; im++)
#pragma unroll
                    for (int in = 0; in < 4; in++)
                        mma16816(acc[im][in], ra[im], rbl[in >> 1][(in & 1) * 2], rbl[in >> 1][(in & 1) * 2 + 1]);
            }
            // A-lo * W-hi
#pragma unroll
            for (int im = 0; im < 4; im++)
                ldmx4(ra[im], sb + 10240 + arow[im] * 80 + akc * 16);
#pragma unroll
            for (int im = 0; im < 4; im++)
#pragma unroll
                for (int in = 0; in < 4; in++)
                    mma16816(acc[im][in], ra[im], rbh[in >> 1][(in & 1) * 2], rbh[in >> 1][(in & 1) * 2 + 1]);
        }
        __syncthreads();
        if (i + 2 < chunks) load_stage(i & 1, i + 2);
    }

    // ---------------- epilogue ----------------
    auto emit = [&](int mm, int cc, float v) {
        if (OUTMODE == 2) {
            split_write(Chi, Clo, (size_t)mm * ldc + coff + cc, fmaxf(v, 0.f));
        } else if (OUTMODE == 3) {
            float s = 1.f / (1.f + expf(-(v + bg[cc])));
            if (cc < 256) {
                zbuf[(size_t)mm * 256 + cc] = s;
            } else {
                int j = cc - 256;
                float rh = s * prevp[(size_t)mm * 256 + j];
                split_write(rhhi, rhlo, (size_t)mm * 256 + j, rh);
            }
        } else if (OUTMODE == 4) {
            float nv = fmaxf(v + bg[512 + cc], 0.f);
            float z = zbuf[(size_t)mm * 256 + cc];
            float pv = prevp[(size_t)mm * 256 + cc];
            outh[(size_t)mm * 256 + cc] = (1.f - z) * nv + z * pv;
        } else {  // 5: fp32 + bias
            outh[(size_t)mm * 256 + cc] = v + bg[cc];
        }
    };
#pragma unroll
    for (int im = 0; im < 4; im++) {
#pragma unroll
        for (int in = 0; in < 4; in++) {
            int m = row0 + wm * 64 + im * 16 + (lane >> 2);
            int c = col0 + wn * 32 + in * 8 + (lane & 3) * 2;
            emit(m, c, acc[im][in][0]);
            emit(m, c + 1, acc[im][in][1]);
            emit(m + 8, c, acc[im][in][2]);
            emit(m + 8, c + 1, acc[im][in][3]);
        }
    }
}

// ---------------- Mt = (Wt^T @ Ws)^T split, cvec = bt @ Ws ----------------
__global__ void computeM(const float* __restrict__ Wt, const float* __restrict__ Ws,
                         const float* __restrict__ bt,
                         fp16* __restrict__ MtH, fp16* __restrict__ MtL,
                         float* __restrict__ cvec)
{
    int k = blockIdx.x, j = threadIdx.x;
    float s = 0.f;
#pragma unroll 8
    for (int a = 0; a < 64; a++) s = fmaf(Wt[a * 256 + k], Ws[a * 256 + j], s);
    split_write(MtH, MtL, (size_t)j * 256 + k, s);
    if (k == 0) {
        float c = 0.f;
#pragma unroll 8
        for (int a = 0; a < 64; a++) c = fmaf(bt[a], Ws[a * 256 + j], c);
        cvec[j] = c;
    }
}

// ---------------- attention (writes in1 cols 256:512) ----------------
__global__ void __launch_bounds__(256) attn_kernel(
    const float* __restrict__ spat, const float* __restrict__ V,
    fp16* __restrict__ hi, fp16* __restrict__ lo)
{
    __shared__ float sp[NE * NH];
    __shared__ float vs[NH];
    __shared__ float attn_s[NE];
    __shared__ float ws[NE];

    int n = blockIdx.x;
    int t = threadIdx.x;

    vs[t] = V[(size_t)n * NH + t];
    const float4* g = (const float4*)(spat + (size_t)n * NE * NH);
    float4* s4 = (float4*)sp;
#pragma unroll
    for (int i = 0; i < 8; i++) s4[t + i * 256] = g[t + i * 256];
    __syncthreads();

    int warp = t >> 5, lane = t & 31;
#pragma unroll
    for (int ei = 0; ei < 4; ei++) {
        int e = warp * 4 + ei;
        float s = 0.f;
#pragma unroll
        for (int i = 0; i < 8; i++)
            s = fmaf(sp[e * NH + lane + i * 32], vs[lane + i * 32], s);
#pragma unroll
        for (int o = 16; o; o >>= 1) s += __shfl_xor_sync(0xffffffffu, s, o);
        if (lane == 0) attn_s[e] = s * 4.0f;
    }
    __syncthreads();

    if (t < 32) {
        float a = attn_s[t];
        float m = a;
#pragma unroll
        for (int o = 16; o; o >>= 1) m = fmaxf(m, __shfl_xor_sync(0xffffffffu, m, o));
        float p = expf(a - m);
        float ssum = p;
#pragma unroll
        for (int o = 16; o; o >>= 1) ssum += __shfl_xor_sync(0xffffffffu, ssum, o);
        ws[t] = p / ssum;
    }
    __syncthreads();

    float acc = 0.f;
#pragma unroll
    for (int e = 0; e < NE; e++) acc = fmaf(ws[e], sp[e * NH + t], acc);
    split_write(hi, lo, (size_t)n * 512 + 256 + t, acc);
}

// ---------------- fused prep: prev split, th split, x_e ----------------
__global__ void __launch_bounds__(256) prep_kernel(
    const float* __restrict__ prev, const float* __restrict__ th,
    const float* __restrict__ xy, const float* __restrict__ Wxy,
    fp16* __restrict__ ph, fp16* __restrict__ pl,
    fp16* __restrict__ i1h, fp16* __restrict__ i1l,
    fp16* __restrict__ ch, fp16* __restrict__ cl)
{
    int n = blockIdx.x, c = threadIdx.x;
    size_t i = (size_t)n * 256 + c;
    split_write(ph, pl, i, prev[i]);
    split_write(i1h, i1l, (size_t)n * 512 + c, th[i]);
    float x0 = xy[n * 2 + 0], x1 = xy[n * 2 + 1];
    float2 w = *(const float2*)&Wxy[c * 2];
    float v = fmaxf(fmaf(x0, w.x, x1 * w.y), 0.f);
    split_write(ch, cl, (size_t)n * 512 + c, v);
}

// ---------------- weight merge + convert ----------------
__global__ void merge_weights(
    const float* __restrict__ Whe, const float* __restrict__ Wih, const float* __restrict__ Whh,
    fp16* __restrict__ WheH, fp16* __restrict__ WheL,
    fp16* __restrict__ Uzr, fp16* __restrict__ Un)
{
    int i = blockIdx.x * 256 + threadIdx.x;
    if (i < 131072) {
        split_write(WheH, WheL, i, Whe[i]);
    } else if (i < 131072 + 393216) {
        int q = i - 131072;
        int j = q / 768, k = q - j * 768;
        int g = j >> 8, r = j & 255;
        float x = (k < 512) ? Wih[g * 131072 + r * 512 + k] : Whh[g * 65536 + r * 256 + (k - 512)];
        Uzr[q] = __float2half_rn(x);
    } else {
        int q = i - 524288;
        int j = q / 768, k = q - j * 768;
        float x = (k < 512) ? Wih[262144 + j * 512 + k] : Whh[131072 + j * 256 + (k - 512)];
        Un[q] = __float2half_rn(x);
    }
}

// ---------------- predict head ----------------
__global__ void __launch_bounds__(256) predict_kernel(
    const float* __restrict__ hid, const float* __restrict__ Wp,
    const float* __restrict__ bp, float* __restrict__ out)
{
    __shared__ float hs[NH];
    int n = blockIdx.x, t = threadIdx.x;
    hs[t] = hid[(size_t)n * NH + t];
    __syncthreads();
    int w = t >> 5, lane = t & 31;
    if (w < OUTD) {
        float s = 0.f;
#pragma unroll
        for (int i = 0; i < 8; i++)
            s = fmaf(hs[lane + i * 32], Wp[w * NH + lane + i * 32], s);
#pragma unroll
        for (int o = 16; o; o >>= 1) s += __shfl_xor_sync(0xffffffffu, s, o);
        if (lane == 0) out[(size_t)n * OUTD + w] = s + bp[w];
    }
}

// ---------------- host launcher ----------------
extern "C" void kernel_launch(void* const* d_in, const int* in_sizes, int n_in,
                              void* d_out, int out_size)
{
    const float* xy   = (const float*)d_in[0];
    const float* th   = (const float*)d_in[1];
    const float* spat = (const float*)d_in[2];
    const float* prev = (const float*)d_in[3];
    const float* Wt   = (const float*)d_in[4];
    const float* bt   = (const float*)d_in[5];
    const float* Ws   = (const float*)d_in[6];
    // d_in[7] = bs: softmax-invariant, dropped.
    const float* Wxy  = (const float*)d_in[8];
    const float* Whe  = (const float*)d_in[9];
    const float* Wih  = (const float*)d_in[10];
    const float* Whh  = (const float*)d_in[11];
    const float* bg   = (const float*)d_in[12];
    const float* Wp   = (const float*)d_in[13];
    const float* bp   = (const float*)d_in[14];

    float* out_pred   = (float*)d_out;
    float* out_hidden = (float*)d_out + NN * OUTD;

    float *pCvec, *pV, *pZ;
    fp16 *pMth, *pMtl, *pIn1h, *pIn1l, *pCath, *pCatl, *pPrevh, *pPrevl, *pRhh, *pRhl;
    fp16 *pWheh, *pWhel, *pUzr, *pUn;
    cudaGetSymbolAddress((void**)&pCvec, g_cvec);
    cudaGetSymbolAddress((void**)&pV, g_V);
    cudaGetSymbolAddress((void**)&pZ, g_z);
    cudaGetSymbolAddress((void**)&pMth, g_Mt_hi);
    cudaGetSymbolAddress((void**)&pMtl, g_Mt_lo);
    cudaGetSymbolAddress((void**)&pIn1h, g_in1_hi);
    cudaGetSymbolAddress((void**)&pIn1l, g_in1_lo);
    cudaGetSymbolAddress((void**)&pCath, g_cat_hi);
    cudaGetSymbolAddress((void**)&pCatl, g_cat_lo);
    cudaGetSymbolAddress((void**)&pPrevh, g_prev_hi);
    cudaGetSymbolAddress((void**)&pPrevl, g_prev_lo);
    cudaGetSymbolAddress((void**)&pRhh, g_rh_hi);
    cudaGetSymbolAddress((void**)&pRhl, g_rh_lo);
    cudaGetSymbolAddress((void**)&pWheh, g_Whe_hi);
    cudaGetSymbolAddress((void**)&pWhel, g_Whe_lo);
    cudaGetSymbolAddress((void**)&pUzr, g_Uzr);
    cudaGetSymbolAddress((void**)&pUn, g_Un);

    const int SM3 = 2 * 40960;   // 3-term stages
    const int SM2 = 2 * 30720;   // 2-term stages
    cudaFuncSetAttribute((const void*)mma3<5, 3>, cudaFuncAttributeMaxDynamicSharedMemorySize, SM3);
    cudaFuncSetAttribute((const void*)mma3<2, 3>, cudaFuncAttributeMaxDynamicSharedMemorySize, SM3);
    cudaFuncSetAttribute((const void*)mma3<3, 2>, cudaFuncAttributeMaxDynamicSharedMemorySize, SM2);
    cudaFuncSetAttribute((const void*)mma3<4, 2>, cudaFuncAttributeMaxDynamicSharedMemorySize, SM2);

    dim3 blk(256);
    const int MB = NN / 128;

    // prep
    merge_weights<<<2816, blk>>>(Whe, Wih, Whh, pWheh, pWhel, pUzr, pUn);
    computeM<<<256, blk>>>(Wt, Ws, bt, pMth, pMtl, pCvec);
    prep_kernel<<<NN, blk>>>(prev, th, xy, Wxy, pPrevh, pPrevl, pIn1h, pIn1l, pCath, pCatl);

    // V = th @ Mt^T + cvec (3-term, fp32 out)
    mma3<5, 3><<<dim3(2, MB), blk, SM3>>>(
        pIn1h, pIn1l, 512, pIn1h, pIn1l, 512, 1024,
        pMth, pMtl, 256, 256,
        nullptr, nullptr, 0, 0, pCvec, nullptr, nullptr, nullptr, nullptr, pV);

    // attention -> Hagg (in1 cols 256:512)
    attn_kernel<<<NN, blk>>>(spat, pV, pIn1h, pIn1l);

    // H_e = relu(in1 @ Whe^T) -> cat[:,256:512]  (3-term)
    mma3<2, 3><<<dim3(2, MB), blk, SM3>>>(
        pIn1h, pIn1l, 512, pIn1h, pIn1l, 512, 512,
        pWheh, pWhel, 512, 512,
        pCath, pCatl, 512, 256, nullptr, nullptr, nullptr, nullptr, nullptr, nullptr);

    // z,r = sigmoid([cat||prev] @ Uzr^T + bg)  (2-term); writes g_z and rh=r*prev
    mma3<3, 2><<<dim3(4, MB), blk, SM2>>>(
        pCath, pCatl, 512, pPrevh, pPrevl, 256, 512,
        pUzr, nullptr, 768, 768,
        nullptr, nullptr, 0, 0, bg, prev, pZ, pRhh, pRhl, nullptr);

    // n = relu([cat||rh] @ Un^T + bg); hidden -> out_hidden  (2-term)
    mma3<4, 2><<<dim3(2, MB), blk, SM2>>>(
        pCath, pCatl, 512, pRhh, pRhl, 256, 512,
        pUn, nullptr, 768, 768,
        nullptr, nullptr, 0, 0, bg, prev, pZ, nullptr, nullptr, out_hidden);

    // predict head
    predict_kernel<<<NN, blk>>>(out_hidden, Wp, bp, out_pred);
}

// round 8
// speedup vs baseline: 1.2231x; 1.0202x over previous
#include <cuda_runtime.h>
#include <cuda_fp16.h>
#include <math.h>
#include <stdint.h>

#define NN 16384
#define NE 32
#define NH 256
#define OUTD 5

typedef __half fp16;

// ---------------- scratch (device globals) ----------------
__device__ __align__(16) float g_cvec[256];
__device__ __align__(16) float g_V[NN * NH];
__device__ __align__(16) float g_z[NN * NH];

__device__ __align__(16) fp16 g_Mt_hi[256 * 256], g_Mt_lo[256 * 256];
__device__ __align__(16) fp16 g_in1_hi[NN * 512], g_in1_lo[NN * 512];  // [th || Hagg]
__device__ __align__(16) fp16 g_cat_hi[NN * 512], g_cat_lo[NN * 512];  // [x_e || H_e]
__device__ __align__(16) fp16 g_prev_hi[NN * 256], g_prev_lo[NN * 256];
__device__ __align__(16) fp16 g_rh_hi[NN * 256],  g_rh_lo[NN * 256];
__device__ __align__(16) fp16 g_Whe[256 * 512];   // single fp16 (2-term)
__device__ __align__(16) fp16 g_Uzr[512 * 768];   // single fp16 (2-term)
__device__ __align__(16) fp16 g_Un[256 * 768];    // single fp16 (2-term)

// ---------------- PTX helpers ----------------
__device__ __forceinline__ uint32_t smem_u32(const void* p) {
    uint32_t a;
    asm("{ .reg .u64 t; cvta.to.shared.u64 t, %1; cvt.u32.u64 %0, t; }" : "=r"(a) : "l"(p));
    return a;
}
__device__ __forceinline__ void cp_async16(uint32_t s, const void* g) {
    asm volatile("cp.async.cg.shared.global [%0], [%1], 16;" :: "r"(s), "l"(g) : "memory");
}
__device__ __forceinline__ void cp_commit() {
    asm volatile("cp.async.commit_group;" ::: "memory");
}
__device__ __forceinline__ void ldmx4(uint32_t* r, uint32_t addr) {
    asm volatile("ldmatrix.sync.aligned.m8n8.x4.shared.b16 {%0,%1,%2,%3}, [%4];"
                 : "=r"(r[0]), "=r"(r[1]), "=r"(r[2]), "=r"(r[3]) : "r"(addr));
}
__device__ __forceinline__ void mma16816(float* c, const uint32_t* a, uint32_t b0, uint32_t b1) {
    asm volatile(
        "mma.sync.aligned.m16n8k16.row.col.f32.f16.f16.f32 "
        "{%0,%1,%2,%3}, {%4,%5,%6,%7}, {%8,%9}, {%0,%1,%2,%3};"
        : "+f"(c[0]), "+f"(c[1]), "+f"(c[2]), "+f"(c[3])
        : "r"(a[0]), "r"(a[1]), "r"(a[2]), "r"(a[3]), "r"(b0), "r"(b1));
}
__device__ __forceinline__ void split_write(fp16* hi, fp16* lo, size_t off, float x) {
    fp16 h = __float2half_rn(x);
    hi[off] = h;
    lo[off] = __float2half_rn(x - __half2float(h));
}

// ---------------- fp16 split GEMM: BM=BN=128, BK=32, 256 thr, 2 CTA/SM ----------
// NTERMS=3: A(hi,lo) x W(hi,lo), 3 terms, 2-stage pipeline (40KB/stage).
// NTERMS=2: A(hi,lo) x W single, 2 terms, 3-stage pipeline (30KB/stage).
// OUTMODE: 2 = relu+fp16 split; 3 = zr epilogue; 4 = n/final epilogue; 5 = fp32+bias.
template <int OUTMODE, int NTERMS>
__global__ void __launch_bounds__(256, 2) mma3(
    const fp16* __restrict__ A1h, const fp16* __restrict__ A1l, int lda1,
    const fp16* __restrict__ A2h, const fp16* __restrict__ A2l, int lda2, int splitK,
    const fp16* __restrict__ Wh, const fp16* __restrict__ Wl, int ldw, int K,
    fp16* __restrict__ Chi, fp16* __restrict__ Clo, int ldc, int coff,
    const float* __restrict__ bg, const float* __restrict__ prevp,
    float* __restrict__ zbuf,
    fp16* __restrict__ rhhi, fp16* __restrict__ rhlo,
    float* __restrict__ outh)
{
    constexpr uint32_t ST = (NTERMS == 3) ? 40960u : 30720u;
    constexpr int STAGES = (NTERMS == 3) ? 2 : 3;
    extern __shared__ char sm[];
    const uint32_t base = smem_u32(sm);
    const int t = threadIdx.x, wid = t >> 5, lane = t & 31;
    const int wm = wid & 1, wn = wid >> 1;
    const int row0 = blockIdx.y * 128, col0 = blockIdx.x * 128;
    const int chunks = K >> 5;

    auto load_stage = [&](int s, int ck) {
        int k0 = ck * 32;
        const fp16 *ah, *al;
        int lda, kk;
        if (k0 < splitK) { ah = A1h; al = A1l; lda = lda1; kk = k0; }
        else             { ah = A2h; al = A2l; lda = lda2; kk = k0 - splitK; }
        uint32_t sb = base + (uint32_t)s * ST;
#pragma unroll
        for (int half = 0; half < 2; half++) {
            int idx = t + half * 256;
            int r = idx >> 2, c = idx & 3;
            uint32_t so = r * 80 + c * 16;
            cp_async16(sb + so,          ah + (size_t)(row0 + r) * lda + kk + c * 8);
            cp_async16(sb + 10240 + so,  al + (size_t)(row0 + r) * lda + kk + c * 8);
            cp_async16(sb + 20480 + so,  Wh + (size_t)(col0 + r) * ldw + k0 + c * 8);
            if (NTERMS == 3)
                cp_async16(sb + 30720 + so, Wl + (size_t)(col0 + r) * ldw + k0 + c * 8);
        }
        cp_commit();
    };

    float acc[4][4][4];
#pragma unroll
    for (int a = 0; a < 4; a++)
#pragma unroll
        for (int b = 0; b < 4; b++)
#pragma unroll
            for (int c = 0; c < 4; c++) acc[a][b][c] = 0.f;

    load_stage(0, 0);
    if (chunks > 1) load_stage(1, 1);

    for (int i = 0; i < chunks; i++) {
        uint32_t sb = base + (uint32_t)(i % STAGES) * ST;
        if (STAGES == 3) {
            if (i + 2 < chunks) {
                load_stage((i + 2) % 3, i + 2);
                asm volatile("cp.async.wait_group 2;" ::: "memory");
            } else if (i + 1 < chunks) {
                asm volatile("cp.async.wait_group 1;" ::: "memory");
            } else {
                asm volatile("cp.async.wait_group 0;" ::: "memory");
            }
        } else {
            if (i + 1 < chunks) asm volatile("cp.async.wait_group 1;" ::: "memory");
            else                asm volatile("cp.async.wait_group 0;" ::: "memory");
        }
        __syncthreads();

#pragma unroll
        for (int ks = 0; ks < 2; ks++) {
            int kb = ks * 16;
            int arow[4];
            int akc = (kb >> 3) + (lane >> 4);
            uint32_t ra[4][4], rbh[2][4];
#pragma unroll
            for (int im = 0; im < 4; im++) {
                arow[im] = wm * 64 + im * 16 + (lane & 15);
                ldmx4(ra[im], sb + arow[im] * 80 + akc * 16);
            }
#pragma unroll
            for (int ib = 0; ib < 2; ib++) {
                int n = wn * 32 + ib * 16 + ((lane & 16) ? 8 : 0) + (lane & 7);
                int kc = (kb >> 3) + ((lane >> 3) & 1);
                ldmx4(rbh[ib], sb + 20480 + n * 80 + kc * 16);
            }
            // A-hi * W-hi
#pragma unroll
            for (int im = 0; im < 4; im++)
#pragma unroll
                for (int in = 0; in < 4; in++)
                    mma16816(acc[im][in], ra[im], rbh[in >> 1][(in & 1) * 2], rbh[in >> 1][(in & 1) * 2 + 1]);
            if (NTERMS == 3) {
                uint32_t rbl[2][4];
#pragma unroll
                for (int ib = 0; ib < 2; ib++) {
                    int n = wn * 32 + ib * 16 + ((lane & 16) ? 8 : 0) + (lane & 7);
                    int kc = (kb >> 3) + ((lane >> 3) & 1);
                    ldmx4(rbl[ib], sb + 30720 + n * 80 + kc * 16);
                }
#pragma unroll
                for (int im = 0; im < 4; im++)
#pragma unroll
                    for (int in = 0; in < 4; in++)
                        mma16816(acc[im][in], ra[im], rbl[in >> 1][(in & 1) * 2], rbl[in >> 1][(in & 1) * 2 + 1]);
            }
            // A-lo * W-hi
#pragma unroll
            for (int im = 0; im < 4; im++)
                ldmx4(ra[im], sb + 10240 + arow[im] * 80 + akc * 16);
#pragma unroll
            for (int im = 0; im < 4; im++)
#pragma unroll
                for (int in = 0; in < 4; in++)
                    mma16816(acc[im][in], ra[im], rbh[in >> 1][(in & 1) * 2], rbh[in >> 1][(in & 1) * 2 + 1]);
        }
        __syncthreads();
        if (STAGES == 2 && i + 2 < chunks) load_stage(i & 1, i + 2);
    }

    // ---------------- epilogue ----------------
    auto emit = [&](int mm, int cc, float v) {
        if (OUTMODE == 2) {
            split_write(Chi, Clo, (size_t)mm * ldc + coff + cc, fmaxf(v, 0.f));
        } else if (OUTMODE == 3) {
            float s = 1.f / (1.f + expf(-(v + bg[cc])));
            if (cc < 256) {
                zbuf[(size_t)mm * 256 + cc] = s;
            } else {
                int j = cc - 256;
                float rh = s * prevp[(size_t)mm * 256 + j];
                split_write(rhhi, rhlo, (size_t)mm * 256 + j, rh);
            }
        } else if (OUTMODE == 4) {
            float nv = fmaxf(v + bg[512 + cc], 0.f);
            float z = zbuf[(size_t)mm * 256 + cc];
            float pv = prevp[(size_t)mm * 256 + cc];
            outh[(size_t)mm * 256 + cc] = (1.f - z) * nv + z * pv;
        } else {  // 5: fp32 + bias
            outh[(size_t)mm * 256 + cc] = v + bg[cc];
        }
    };
#pragma unroll
    for (int im = 0; im < 4; im++) {
#pragma unroll
        for (int in = 0; in < 4; in++) {
            int m = row0 + wm * 64 + im * 16 + (lane >> 2);
            int c = col0 + wn * 32 + in * 8 + (lane & 3) * 2;
            emit(m, c, acc[im][in][0]);
            emit(m, c + 1, acc[im][in][1]);
            emit(m + 8, c, acc[im][in][2]);
            emit(m + 8, c + 1, acc[im][in][3]);
        }
    }
}

// ---------------- Mt = (Wt^T @ Ws)^T split, cvec = bt @ Ws ----------------
__global__ void computeM(const float* __restrict__ Wt, const float* __restrict__ Ws,
                         const float* __restrict__ bt,
                         fp16* __restrict__ MtH, fp16* __restrict__ MtL,
                         float* __restrict__ cvec)
{
    int k = blockIdx.x, j = threadIdx.x;
    float s = 0.f;
#pragma unroll 8
    for (int a = 0; a < 64; a++) s = fmaf(Wt[a * 256 + k], Ws[a * 256 + j], s);
    split_write(MtH, MtL, (size_t)j * 256 + k, s);
    if (k == 0) {
        float c = 0.f;
#pragma unroll 8
        for (int a = 0; a < 64; a++) c = fmaf(bt[a], Ws[a * 256 + j], c);
        cvec[j] = c;
    }
}

// ---------------- attention (writes in1 cols 256:512) ----------------
__global__ void __launch_bounds__(256) attn_kernel(
    const float* __restrict__ spat, const float* __restrict__ V,
    fp16* __restrict__ hi, fp16* __restrict__ lo)
{
    __shared__ float sp[NE * NH];
    __shared__ float vs[NH];
    __shared__ float attn_s[NE];
    __shared__ float ws[NE];

    int n = blockIdx.x;
    int t = threadIdx.x;

    vs[t] = V[(size_t)n * NH + t];
    const float4* g = (const float4*)(spat + (size_t)n * NE * NH);
    float4* s4 = (float4*)sp;
#pragma unroll
    for (int i = 0; i < 8; i++) s4[t + i * 256] = g[t + i * 256];
    __syncthreads();

    int warp = t >> 5, lane = t & 31;
#pragma unroll
    for (int ei = 0; ei < 4; ei++) {
        int e = warp * 4 + ei;
        float s = 0.f;
#pragma unroll
        for (int i = 0; i < 8; i++)
            s = fmaf(sp[e * NH + lane + i * 32], vs[lane + i * 32], s);
#pragma unroll
        for (int o = 16; o; o >>= 1) s += __shfl_xor_sync(0xffffffffu, s, o);
        if (lane == 0) attn_s[e] = s * 4.0f;
    }
    __syncthreads();

    if (t < 32) {
        float a = attn_s[t];
        float m = a;
#pragma unroll
        for (int o = 16; o; o >>= 1) m = fmaxf(m, __shfl_xor_sync(0xffffffffu, m, o));
        float p = expf(a - m);
        float ssum = p;
#pragma unroll
        for (int o = 16; o; o >>= 1) ssum += __shfl_xor_sync(0xffffffffu, ssum, o);
        ws[t] = p / ssum;
    }
    __syncthreads();

    float acc = 0.f;
#pragma unroll
    for (int e = 0; e < NE; e++) acc = fmaf(ws[e], sp[e * NH + t], acc);
    split_write(hi, lo, (size_t)n * 512 + 256 + t, acc);
}

// ---------------- fused prep: prev split, th split, x_e ----------------
__global__ void __launch_bounds__(256) prep_kernel(
    const float* __restrict__ prev, const float* __restrict__ th,
    const float* __restrict__ xy, const float* __restrict__ Wxy,
    fp16* __restrict__ ph, fp16* __restrict__ pl,
    fp16* __restrict__ i1h, fp16* __restrict__ i1l,
    fp16* __restrict__ ch, fp16* __restrict__ cl)
{
    int n = blockIdx.x, c = threadIdx.x;
    size_t i = (size_t)n * 256 + c;
    split_write(ph, pl, i, prev[i]);
    split_write(i1h, i1l, (size_t)n * 512 + c, th[i]);
    float x0 = xy[n * 2 + 0], x1 = xy[n * 2 + 1];
    float2 w = *(const float2*)&Wxy[c * 2];
    float v = fmaxf(fmaf(x0, w.x, x1 * w.y), 0.f);
    split_write(ch, cl, (size_t)n * 512 + c, v);
}

// ---------------- weight merge + convert ----------------
__global__ void merge_weights(
    const float* __restrict__ Whe, const float* __restrict__ Wih, const float* __restrict__ Whh,
    fp16* __restrict__ WheO,
    fp16* __restrict__ Uzr, fp16* __restrict__ Un)
{
    int i = blockIdx.x * 256 + threadIdx.x;
    if (i < 131072) {
        WheO[i] = __float2half_rn(Whe[i]);
    } else if (i < 131072 + 393216) {
        int q = i - 131072;
        int j = q / 768, k = q - j * 768;
        int g = j >> 8, r = j & 255;
        float x = (k < 512) ? Wih[g * 131072 + r * 512 + k] : Whh[g * 65536 + r * 256 + (k - 512)];
        Uzr[q] = __float2half_rn(x);
    } else {
        int q = i - 524288;
        int j = q / 768, k = q - j * 768;
        float x = (k < 512) ? Wih[262144 + j * 512 + k] : Whh[131072 + j * 256 + (k - 512)];
        Un[q] = __float2half_rn(x);
    }
}

// ---------------- predict head ----------------
__global__ void __launch_bounds__(256) predict_kernel(
    const float* __restrict__ hid, const float* __restrict__ Wp,
    const float* __restrict__ bp, float* __restrict__ out)
{
    __shared__ float hs[NH];
    int n = blockIdx.x, t = threadIdx.x;
    hs[t] = hid[(size_t)n * NH + t];
    __syncthreads();
    int w = t >> 5, lane = t & 31;
    if (w < OUTD) {
        float s = 0.f;
#pragma unroll
        for (int i = 0; i < 8; i++)
            s = fmaf(hs[lane + i * 32], Wp[w * NH + lane + i * 32], s);
#pragma unroll
        for (int o = 16; o; o >>= 1) s += __shfl_xor_sync(0xffffffffu, s, o);
        if (lane == 0) out[(size_t)n * OUTD + w] = s + bp[w];
    }
}

// ---------------- host launcher ----------------
extern "C" void kernel_launch(void* const* d_in, const int* in_sizes, int n_in,
                              void* d_out, int out_size)
{
    const float* xy   = (const float*)d_in[0];
    const float* th   = (const float*)d_in[1];
    const float* spat = (const float*)d_in[2];
    const float* prev = (const float*)d_in[3];
    const float* Wt   = (const float*)d_in[4];
    const float* bt   = (const float*)d_in[5];
    const float* Ws   = (const float*)d_in[6];
    // d_in[7] = bs: softmax-invariant, dropped.
    const float* Wxy  = (const float*)d_in[8];
    const float* Whe  = (const float*)d_in[9];
    const float* Wih  = (const float*)d_in[10];
    const float* Whh  = (const float*)d_in[11];
    const float* bg   = (const float*)d_in[12];
    const float* Wp   = (const float*)d_in[13];
    const float* bp   = (const float*)d_in[14];

    float* out_pred   = (float*)d_out;
    float* out_hidden = (float*)d_out + NN * OUTD;

    float *pCvec, *pV, *pZ;
    fp16 *pMth, *pMtl, *pIn1h, *pIn1l, *pCath, *pCatl, *pPrevh, *pPrevl, *pRhh, *pRhl;
    fp16 *pWhe, *pUzr, *pUn;
    cudaGetSymbolAddress((void**)&pCvec, g_cvec);
    cudaGetSymbolAddress((void**)&pV, g_V);
    cudaGetSymbolAddress((void**)&pZ, g_z);
    cudaGetSymbolAddress((void**)&pMth, g_Mt_hi);
    cudaGetSymbolAddress((void**)&pMtl, g_Mt_lo);
    cudaGetSymbolAddress((void**)&pIn1h, g_in1_hi);
    cudaGetSymbolAddress((void**)&pIn1l, g_in1_lo);
    cudaGetSymbolAddress((void**)&pCath, g_cat_hi);
    cudaGetSymbolAddress((void**)&pCatl, g_cat_lo);
    cudaGetSymbolAddress((void**)&pPrevh, g_prev_hi);
    cudaGetSymbolAddress((void**)&pPrevl, g_prev_lo);
    cudaGetSymbolAddress((void**)&pRhh, g_rh_hi);
    cudaGetSymbolAddress((void**)&pRhl, g_rh_lo);
    cudaGetSymbolAddress((void**)&pWhe, g_Whe);
    cudaGetSymbolAddress((void**)&pUzr, g_Uzr);
    cudaGetSymbolAddress((void**)&pUn, g_Un);

    const int SM3 = 2 * 40960;   // 3-term, 2-stage
    const int SM2 = 3 * 30720;   // 2-term, 3-stage
    cudaFuncSetAttribute((const void*)mma3<5, 3>, cudaFuncAttributeMaxDynamicSharedMemorySize, SM3);
    cudaFuncSetAttribute((const void*)mma3<2, 2>, cudaFuncAttributeMaxDynamicSharedMemorySize, SM2);
    cudaFuncSetAttribute((const void*)mma3<3, 2>, cudaFuncAttributeMaxDynamicSharedMemorySize, SM2);
    cudaFuncSetAttribute((const void*)mma3<4, 2>, cudaFuncAttributeMaxDynamicSharedMemorySize, SM2);

    dim3 blk(256);
    const int MB = NN / 128;

    // prep
    merge_weights<<<2816, blk>>>(Whe, Wih, Whh, pWhe, pUzr, pUn);
    computeM<<<256, blk>>>(Wt, Ws, bt, pMth, pMtl, pCvec);
    prep_kernel<<<NN, blk>>>(prev, th, xy, Wxy, pPrevh, pPrevl, pIn1h, pIn1l, pCath, pCatl);

    // V = th @ Mt^T + cvec (3-term, fp32 out)
    mma3<5, 3><<<dim3(2, MB), blk, SM3>>>(
        pIn1h, pIn1l, 512, pIn1h, pIn1l, 512, 1024,
        pMth, pMtl, 256, 256,
        nullptr, nullptr, 0, 0, pCvec, nullptr, nullptr, nullptr, nullptr, pV);

    // attention -> Hagg (in1 cols 256:512)
    attn_kernel<<<NN, blk>>>(spat, pV, pIn1h, pIn1l);

    // H_e = relu(in1 @ Whe^T) -> cat[:,256:512]  (2-term)
    mma3<2, 2><<<dim3(2, MB), blk, SM2>>>(
        pIn1h, pIn1l, 512, pIn1h, pIn1l, 512, 512,
        pWhe, nullptr, 512, 512,
        pCath, pCatl, 512, 256, nullptr, nullptr, nullptr, nullptr, nullptr, nullptr);

    // z,r = sigmoid([cat||prev] @ Uzr^T + bg)  (2-term); writes g_z and rh=r*prev
    mma3<3, 2><<<dim3(4, MB), blk, SM2>>>(
        pCath, pCatl, 512, pPrevh, pPrevl, 256, 512,
        pUzr, nullptr, 768, 768,
        nullptr, nullptr, 0, 0, bg, prev, pZ, pRhh, pRhl, nullptr);

    // n = relu([cat||rh] @ Un^T + bg); hidden -> out_hidden  (2-term)
    mma3<4, 2><<<dim3(2, MB), blk, SM2>>>(
        pCath, pCatl, 512, pRhh, pRhl, 256, 512,
        pUn, nullptr, 768, 768,
        nullptr, nullptr, 0, 0, bg, prev, pZ, nullptr, nullptr, out_hidden);

    // predict head
    predict_kernel<<<NN, blk>>>(out_hidden, Wp, bp, out_pred);
}

// round 9
// speedup vs baseline: 1.4673x; 1.1997x over previous
#include <cuda_runtime.h>
#include <cuda_fp16.h>
#include <math.h>
#include <stdint.h>

#define NN 16384
#define NE 32
#define NH 256
#define OUTD 5

typedef __half fp16;

// ---------------- scratch (device globals) ----------------
__device__ __align__(16) float g_cvec[256];
__device__ __align__(16) float g_V[NN * NH];
__device__ __align__(16) float g_z[NN * NH];

__device__ __align__(16) fp16 g_Mt_hi[256 * 256], g_Mt_lo[256 * 256];
__device__ __align__(16) fp16 g_in1_hi[NN * 512], g_in1_lo[NN * 512];  // [th || Hagg] hi/lo
__device__ __align__(16) fp16 g_cat[NN * 512];                          // [x_e || H_e] single
__device__ __align__(16) fp16 g_prev[NN * 256];                         // single
__device__ __align__(16) fp16 g_rh[NN * 256];                           // single
__device__ __align__(16) fp16 g_Whe[256 * 512];   // single fp16 (2-term GEMM: A split)
__device__ __align__(16) fp16 g_Uzr[512 * 768];   // single fp16 (1-term GEMM)
__device__ __align__(16) fp16 g_Un[256 * 768];    // single fp16 (1-term GEMM)

// ---------------- PTX helpers ----------------
__device__ __forceinline__ uint32_t smem_u32(const void* p) {
    uint32_t a;
    asm("{ .reg .u64 t; cvta.to.shared.u64 t, %1; cvt.u32.u64 %0, t; }" : "=r"(a) : "l"(p));
    return a;
}
__device__ __forceinline__ void cp_async16(uint32_t s, const void* g) {
    asm volatile("cp.async.cg.shared.global [%0], [%1], 16;" :: "r"(s), "l"(g) : "memory");
}
__device__ __forceinline__ void cp_commit() {
    asm volatile("cp.async.commit_group;" ::: "memory");
}
__device__ __forceinline__ void ldmx4(uint32_t* r, uint32_t addr) {
    asm volatile("ldmatrix.sync.aligned.m8n8.x4.shared.b16 {%0,%1,%2,%3}, [%4];"
                 : "=r"(r[0]), "=r"(r[1]), "=r"(r[2]), "=r"(r[3]) : "r"(addr));
}
__device__ __forceinline__ void mma16816(float* c, const uint32_t* a, uint32_t b0, uint32_t b1) {
    asm volatile(
        "mma.sync.aligned.m16n8k16.row.col.f32.f16.f16.f32 "
        "{%0,%1,%2,%3}, {%4,%5,%6,%7}, {%8,%9}, {%0,%1,%2,%3};"
        : "+f"(c[0]), "+f"(c[1]), "+f"(c[2]), "+f"(c[3])
        : "r"(a[0]), "r"(a[1]), "r"(a[2]), "r"(a[3]), "r"(b0), "r"(b1));
}
__device__ __forceinline__ void split_write(fp16* hi, fp16* lo, size_t off, float x) {
    fp16 h = __float2half_rn(x);
    hi[off] = h;
    lo[off] = __float2half_rn(x - __half2float(h));
}

// ---------------- fp16 split GEMM: BM=BN=128, BK=32, 256 thr, 2 CTA/SM ----------
// NTERMS=3: A(hi,lo) x W(hi,lo), 3 terms, 2-stage (40KB/stage).
// NTERMS=2: A(hi,lo) x W single,  2 terms, 3-stage (30KB/stage).
// NTERMS=1: A single  x W single, 1 term,  4-stage (20KB/stage).
// OUTMODE: 2 = relu + single fp16; 3 = zr epilogue; 4 = n/final epilogue; 5 = fp32+bias.
template <int OUTMODE, int NTERMS>
__global__ void __launch_bounds__(256, 2) mma3(
    const fp16* __restrict__ A1h, const fp16* __restrict__ A1l, int lda1,
    const fp16* __restrict__ A2h, const fp16* __restrict__ A2l, int lda2, int splitK,
    const fp16* __restrict__ Wh, const fp16* __restrict__ Wl, int ldw, int K,
    fp16* __restrict__ Cout, int ldc, int coff,
    const float* __restrict__ bg, const float* __restrict__ prevp,
    float* __restrict__ zbuf,
    fp16* __restrict__ rhout,
    float* __restrict__ outh)
{
    constexpr uint32_t ST = (NTERMS == 3) ? 40960u : (NTERMS == 2 ? 30720u : 20480u);
    constexpr int STAGES = (NTERMS == 3) ? 2 : (NTERMS == 2 ? 3 : 4);
    constexpr uint32_t WOFF = (NTERMS == 1) ? 10240u : 20480u;
    extern __shared__ char sm[];
    const uint32_t base = smem_u32(sm);
    const int t = threadIdx.x, wid = t >> 5, lane = t & 31;
    const int wm = wid & 1, wn = wid >> 1;
    const int row0 = blockIdx.y * 128, col0 = blockIdx.x * 128;
    const int chunks = K >> 5;

    auto load_stage = [&](int s, int ck) {
        int k0 = ck * 32;
        const fp16 *ah, *al;
        int lda, kk;
        if (k0 < splitK) { ah = A1h; al = A1l; lda = lda1; kk = k0; }
        else             { ah = A2h; al = A2l; lda = lda2; kk = k0 - splitK; }
        uint32_t sb = base + (uint32_t)s * ST;
#pragma unroll
        for (int half = 0; half < 2; half++) {
            int idx = t + half * 256;
            int r = idx >> 2, c = idx & 3;
            uint32_t so = r * 80 + c * 16;
            cp_async16(sb + so, ah + (size_t)(row0 + r) * lda + kk + c * 8);
            if (NTERMS >= 2)
                cp_async16(sb + 10240 + so, al + (size_t)(row0 + r) * lda + kk + c * 8);
            cp_async16(sb + WOFF + so, Wh + (size_t)(col0 + r) * ldw + k0 + c * 8);
            if (NTERMS == 3)
                cp_async16(sb + 30720 + so, Wl + (size_t)(col0 + r) * ldw + k0 + c * 8);
        }
        cp_commit();
    };

    float acc[4][4][4];
#pragma unroll
    for (int a = 0; a < 4; a++)
#pragma unroll
        for (int b = 0; b < 4; b++)
#pragma unroll
            for (int c = 0; c < 4; c++) acc[a][b][c] = 0.f;

    int issued = 0;
    for (; issued < STAGES - 1 && issued < chunks; issued++)
        load_stage(issued % STAGES, issued);

    for (int i = 0; i < chunks; i++) {
        if (issued < chunks) { load_stage(issued % STAGES, issued); issued++; }
        int pend = chunks - 1 - i;
        if (pend > STAGES - 1) pend = STAGES - 1;
        if (pend == 0)      asm volatile("cp.async.wait_group 0;" ::: "memory");
        else if (pend == 1) asm volatile("cp.async.wait_group 1;" ::: "memory");
        else if (pend == 2) asm volatile("cp.async.wait_group 2;" ::: "memory");
        else                asm volatile("cp.async.wait_group 3;" ::: "memory");
        __syncthreads();

        uint32_t sb = base + (uint32_t)(i % STAGES) * ST;
#pragma unroll
        for (int ks = 0; ks < 2; ks++) {
            int kb = ks * 16;
            int arow[4];
            int akc = (kb >> 3) + (lane >> 4);
            uint32_t ra[4][4], rbh[2][4];
#pragma unroll
            for (int im = 0; im < 4; im++) {
                arow[im] = wm * 64 + im * 16 + (lane & 15);
                ldmx4(ra[im], sb + arow[im] * 80 + akc * 16);
            }
#pragma unroll
            for (int ib = 0; ib < 2; ib++) {
                int n = wn * 32 + ib * 16 + ((lane & 16) ? 8 : 0) + (lane & 7);
                int kc = (kb >> 3) + ((lane >> 3) & 1);
                ldmx4(rbh[ib], sb + WOFF + n * 80 + kc * 16);
            }
            // A-hi * W-hi
#pragma unroll
            for (int im = 0; im < 4; im++)
#pragma unroll
                for (int in = 0; in < 4; in++)
                    mma16816(acc[im][in], ra[im], rbh[in >> 1][(in & 1) * 2], rbh[in >> 1][(in & 1) * 2 + 1]);
            if (NTERMS == 3) {
                uint32_t rbl[2][4];
#pragma unroll
                for (int ib = 0; ib < 2; ib++) {
                    int n = wn * 32 + ib * 16 + ((lane & 16) ? 8 : 0) + (lane & 7);
                    int kc = (kb >> 3) + ((lane >> 3) & 1);
                    ldmx4(rbl[ib], sb + 30720 + n * 80 + kc * 16);
                }
#pragma unroll
                for (int im = 0; im < 4; im++)
#pragma unroll
                    for (int in = 0; in < 4; in++)
                        mma16816(acc[im][in], ra[im], rbl[in >> 1][(in & 1) * 2], rbl[in >> 1][(in & 1) * 2 + 1]);
            }
            if (NTERMS >= 2) {
                // A-lo * W-hi
#pragma unroll
                for (int im = 0; im < 4; im++)
                    ldmx4(ra[im], sb + 10240 + arow[im] * 80 + akc * 16);
#pragma unroll
                for (int im = 0; im < 4; im++)
#pragma unroll
                    for (int in = 0; in < 4; in++)
                        mma16816(acc[im][in], ra[im], rbh[in >> 1][(in & 1) * 2], rbh[in >> 1][(in & 1) * 2 + 1]);
            }
        }
        __syncthreads();
    }

    // ---------------- epilogue ----------------
    auto emit = [&](int mm, int cc, float v) {
        if (OUTMODE == 2) {
            Cout[(size_t)mm * ldc + coff + cc] = __float2half_rn(fmaxf(v, 0.f));
        } else if (OUTMODE == 3) {
            float s = 1.f / (1.f + expf(-(v + bg[cc])));
            if (cc < 256) {
                zbuf[(size_t)mm * 256 + cc] = s;
            } else {
                int j = cc - 256;
                rhout[(size_t)mm * 256 + j] = __float2half_rn(s * prevp[(size_t)mm * 256 + j]);
            }
        } else if (OUTMODE == 4) {
            float nv = fmaxf(v + bg[512 + cc], 0.f);
            float z = zbuf[(size_t)mm * 256 + cc];
            float pv = prevp[(size_t)mm * 256 + cc];
            outh[(size_t)mm * 256 + cc] = (1.f - z) * nv + z * pv;
        } else {  // 5: fp32 + bias
            outh[(size_t)mm * 256 + cc] = v + bg[cc];
        }
    };
#pragma unroll
    for (int im = 0; im < 4; im++) {
#pragma unroll
        for (int in = 0; in < 4; in++) {
            int m = row0 + wm * 64 + im * 16 + (lane >> 2);
            int c = col0 + wn * 32 + in * 8 + (lane & 3) * 2;
            emit(m, c, acc[im][in][0]);
            emit(m, c + 1, acc[im][in][1]);
            emit(m + 8, c, acc[im][in][2]);
            emit(m + 8, c + 1, acc[im][in][3]);
        }
    }
}

// ---------------- Mt = (Wt^T @ Ws)^T split, cvec = bt @ Ws ----------------
__global__ void computeM(const float* __restrict__ Wt, const float* __restrict__ Ws,
                         const float* __restrict__ bt,
                         fp16* __restrict__ MtH, fp16* __restrict__ MtL,
                         float* __restrict__ cvec)
{
    int k = blockIdx.x, j = threadIdx.x;
    float s = 0.f;
#pragma unroll 8
    for (int a = 0; a < 64; a++) s = fmaf(Wt[a * 256 + k], Ws[a * 256 + j], s);
    split_write(MtH, MtL, (size_t)j * 256 + k, s);
    if (k == 0) {
        float c = 0.f;
#pragma unroll 8
        for (int a = 0; a < 64; a++) c = fmaf(bt[a], Ws[a * 256 + j], c);
        cvec[j] = c;
    }
}

// ---------------- attention (writes in1 cols 256:512, hi/lo) ----------------
__global__ void __launch_bounds__(256) attn_kernel(
    const float* __restrict__ spat, const float* __restrict__ V,
    fp16* __restrict__ hi, fp16* __restrict__ lo)
{
    __shared__ float sp[NE * NH];
    __shared__ float vs[NH];
    __shared__ float attn_s[NE];
    __shared__ float ws[NE];

    int n = blockIdx.x;
    int t = threadIdx.x;

    vs[t] = V[(size_t)n * NH + t];
    const float4* g = (const float4*)(spat + (size_t)n * NE * NH);
    float4* s4 = (float4*)sp;
#pragma unroll
    for (int i = 0; i < 8; i++) s4[t + i * 256] = g[t + i * 256];
    __syncthreads();

    int warp = t >> 5, lane = t & 31;
#pragma unroll
    for (int ei = 0; ei < 4; ei++) {
        int e = warp * 4 + ei;
        float s = 0.f;
#pragma unroll
        for (int i = 0; i < 8; i++)
            s = fmaf(sp[e * NH + lane + i * 32], vs[lane + i * 32], s);
#pragma unroll
        for (int o = 16; o; o >>= 1) s += __shfl_xor_sync(0xffffffffu, s, o);
        if (lane == 0) attn_s[e] = s * 4.0f;
    }
    __syncthreads();

    if (t < 32) {
        float a = attn_s[t];
        float m = a;
#pragma unroll
        for (int o = 16; o; o >>= 1) m = fmaxf(m, __shfl_xor_sync(0xffffffffu, m, o));
        float p = expf(a - m);
        float ssum = p;
#pragma unroll
        for (int o = 16; o; o >>= 1) ssum += __shfl_xor_sync(0xffffffffu, ssum, o);
        ws[t] = p / ssum;
    }
    __syncthreads();

    float acc = 0.f;
#pragma unroll
    for (int e = 0; e < NE; e++) acc = fmaf(ws[e], sp[e * NH + t], acc);
    split_write(hi, lo, (size_t)n * 512 + 256 + t, acc);
}

// ---------------- fused prep: prev fp16, th split, x_e ----------------
__global__ void __launch_bounds__(256) prep_kernel(
    const float* __restrict__ prev, const float* __restrict__ th,
    const float* __restrict__ xy, const float* __restrict__ Wxy,
    fp16* __restrict__ ph,
    fp16* __restrict__ i1h, fp16* __restrict__ i1l,
    fp16* __restrict__ ch)
{
    int n = blockIdx.x, c = threadIdx.x;
    size_t i = (size_t)n * 256 + c;
    ph[i] = __float2half_rn(prev[i]);
    split_write(i1h, i1l, (size_t)n * 512 + c, th[i]);
    float x0 = xy[n * 2 + 0], x1 = xy[n * 2 + 1];
    float2 w = *(const float2*)&Wxy[c * 2];
    float v = fmaxf(fmaf(x0, w.x, x1 * w.y), 0.f);
    ch[(size_t)n * 512 + c] = __float2half_rn(v);
}

// ---------------- weight merge + convert ----------------
__global__ void merge_weights(
    const float* __restrict__ Whe, const float* __restrict__ Wih, const float* __restrict__ Whh,
    fp16* __restrict__ WheO,
    fp16* __restrict__ Uzr, fp16* __restrict__ Un)
{
    int i = blockIdx.x * 256 + threadIdx.x;
    if (i < 131072) {
        WheO[i] = __float2half_rn(Whe[i]);
    } else if (i < 131072 + 393216) {
        int q = i - 131072;
        int j = q / 768, k = q - j * 768;
        int g = j >> 8, r = j & 255;
        float x = (k < 512) ? Wih[g * 131072 + r * 512 + k] : Whh[g * 65536 + r * 256 + (k - 512)];
        Uzr[q] = __float2half_rn(x);
    } else {
        int q = i - 524288;
        int j = q / 768, k = q - j * 768;
        float x = (k < 512) ? Wih[262144 + j * 512 + k] : Whh[131072 + j * 256 + (k - 512)];
        Un[q] = __float2half_rn(x);
    }
}

// ---------------- predict head ----------------
__global__ void __launch_bounds__(256) predict_kernel(
    const float* __restrict__ hid, const float* __restrict__ Wp,
    const float* __restrict__ bp, float* __restrict__ out)
{
    __shared__ float hs[NH];
    int n = blockIdx.x, t = threadIdx.x;
    hs[t] = hid[(size_t)n * NH + t];
    __syncthreads();
    int w = t >> 5, lane = t & 31;
    if (w < OUTD) {
        float s = 0.f;
#pragma unroll
        for (int i = 0; i < 8; i++)
            s = fmaf(hs[lane + i * 32], Wp[w * NH + lane + i * 32], s);
#pragma unroll
        for (int o = 16; o; o >>= 1) s += __shfl_xor_sync(0xffffffffu, s, o);
        if (lane == 0) out[(size_t)n * OUTD + w] = s + bp[w];
    }
}

// ---------------- host launcher ----------------
extern "C" void kernel_launch(void* const* d_in, const int* in_sizes, int n_in,
                              void* d_out, int out_size)
{
    const float* xy   = (const float*)d_in[0];
    const float* th   = (const float*)d_in[1];
    const float* spat = (const float*)d_in[2];
    const float* prev = (const float*)d_in[3];
    const float* Wt   = (const float*)d_in[4];
    const float* bt   = (const float*)d_in[5];
    const float* Ws   = (const float*)d_in[6];
    // d_in[7] = bs: softmax-invariant, dropped.
    const float* Wxy  = (const float*)d_in[8];
    const float* Whe  = (const float*)d_in[9];
    const float* Wih  = (const float*)d_in[10];
    const float* Whh  = (const float*)d_in[11];
    const float* bg   = (const float*)d_in[12];
    const float* Wp   = (const float*)d_in[13];
    const float* bp   = (const float*)d_in[14];

    float* out_pred   = (float*)d_out;
    float* out_hidden = (float*)d_out + NN * OUTD;

    float *pCvec, *pV, *pZ;
    fp16 *pMth, *pMtl, *pIn1h, *pIn1l, *pCat, *pPrev, *pRh;
    fp16 *pWhe, *pUzr, *pUn;
    cudaGetSymbolAddress((void**)&pCvec, g_cvec);
    cudaGetSymbolAddress((void**)&pV, g_V);
    cudaGetSymbolAddress((void**)&pZ, g_z);
    cudaGetSymbolAddress((void**)&pMth, g_Mt_hi);
    cudaGetSymbolAddress((void**)&pMtl, g_Mt_lo);
    cudaGetSymbolAddress((void**)&pIn1h, g_in1_hi);
    cudaGetSymbolAddress((void**)&pIn1l, g_in1_lo);
    cudaGetSymbolAddress((void**)&pCat, g_cat);
    cudaGetSymbolAddress((void**)&pPrev, g_prev);
    cudaGetSymbolAddress((void**)&pRh, g_rh);
    cudaGetSymbolAddress((void**)&pWhe, g_Whe);
    cudaGetSymbolAddress((void**)&pUzr, g_Uzr);
    cudaGetSymbolAddress((void**)&pUn, g_Un);

    const int SM3 = 2 * 40960;   // 3-term, 2-stage
    const int SM2 = 3 * 30720;   // 2-term, 3-stage
    const int SM1 = 4 * 20480;   // 1-term, 4-stage
    cudaFuncSetAttribute((const void*)mma3<5, 3>, cudaFuncAttributeMaxDynamicSharedMemorySize, SM3);
    cudaFuncSetAttribute((const void*)mma3<2, 2>, cudaFuncAttributeMaxDynamicSharedMemorySize, SM2);
    cudaFuncSetAttribute((const void*)mma3<3, 1>, cudaFuncAttributeMaxDynamicSharedMemorySize, SM1);
    cudaFuncSetAttribute((const void*)mma3<4, 1>, cudaFuncAttributeMaxDynamicSharedMemorySize, SM1);

    dim3 blk(256);
    const int MB = NN / 128;

    // prep
    merge_weights<<<2816, blk>>>(Whe, Wih, Whh, pWhe, pUzr, pUn);
    computeM<<<256, blk>>>(Wt, Ws, bt, pMth, pMtl, pCvec);
    prep_kernel<<<NN, blk>>>(prev, th, xy, Wxy, pPrev, pIn1h, pIn1l, pCat);

    // V = th @ Mt^T + cvec (3-term, fp32 out)
    mma3<5, 3><<<dim3(2, MB), blk, SM3>>>(
        pIn1h, pIn1l, 512, pIn1h, pIn1l, 512, 1024,
        pMth, pMtl, 256, 256,
        nullptr, 0, 0, pCvec, nullptr, nullptr, nullptr, pV);

    // attention -> Hagg (in1 cols 256:512)
    attn_kernel<<<NN, blk>>>(spat, pV, pIn1h, pIn1l);

    // H_e = relu(in1 @ Whe^T) -> cat[:,256:512]  (2-term, single fp16 out)
    mma3<2, 2><<<dim3(2, MB), blk, SM2>>>(
        pIn1h, pIn1l, 512, pIn1h, pIn1l, 512, 512,
        pWhe, nullptr, 512, 512,
        pCat, 512, 256, nullptr, nullptr, nullptr, nullptr, nullptr);

    // z,r = sigmoid([cat||prev] @ Uzr^T + bg)  (1-term); writes g_z and rh=r*prev
    mma3<3, 1><<<dim3(4, MB), blk, SM1>>>(
        pCat, nullptr, 512, pPrev, nullptr, 256, 512,
        pUzr, nullptr, 768, 768,
        nullptr, 0, 0, bg, prev, pZ, pRh, nullptr);

    // n = relu([cat||rh] @ Un^T + bg); hidden -> out_hidden  (1-term)
    mma3<4, 1><<<dim3(2, MB), blk, SM1>>>(
        pCat, nullptr, 512, pRh, nullptr, 256, 512,
        pUn, nullptr, 768, 768,
        nullptr, 0, 0, bg, prev, pZ, nullptr, out_hidden);

    // predict head
    predict_kernel<<<NN, blk>>>(out_hidden, Wp, bp, out_pred);
}

// round 11
// speedup vs baseline: 1.5403x; 1.0497x over previous
#include <cuda_runtime.h>
#include <cuda_fp16.h>
#include <math.h>
#include <stdint.h>

#define NN 16384
#define NE 32
#define NH 256
#define OUTD 5

typedef __half fp16;

// ---------------- scratch (device globals) ----------------
__device__ __align__(16) float g_cvec[256];
__device__ __align__(16) float g_V[NN * NH];
__device__ __align__(16) float g_z[NN * NH];

__device__ __align__(16) fp16 g_Mt_hi[256 * 256], g_Mt_lo[256 * 256];
__device__ __align__(16) fp16 g_in1_hi[NN * 512], g_in1_lo[NN * 512];  // [th || Hagg]
__device__ __align__(16) fp16 g_cat[NN * 512];                          // [x_e || H_e]
__device__ __align__(16) fp16 g_prev[NN * 256];
__device__ __align__(16) fp16 g_rh[NN * 256];
__device__ __align__(16) fp16 g_Whe[256 * 512];
__device__ __align__(16) fp16 g_Uzr[512 * 768];
__device__ __align__(16) fp16 g_Un[256 * 768];

// ---------------- PTX helpers ----------------
__device__ __forceinline__ uint32_t smem_u32(const void* p) {
    uint32_t a;
    asm("{ .reg .u64 t; cvta.to.shared.u64 t, %1; cvt.u32.u64 %0, t; }" : "=r"(a) : "l"(p));
    return a;
}
__device__ __forceinline__ void cp_async16(uint32_t s, const void* g) {
    asm volatile("cp.async.cg.shared.global [%0], [%1], 16;" :: "r"(s), "l"(g) : "memory");
}
__device__ __forceinline__ void cp_commit() {
    asm volatile("cp.async.commit_group;" ::: "memory");
}
__device__ __forceinline__ void ldmx4(uint32_t* r, uint32_t addr) {
    asm volatile("ldmatrix.sync.aligned.m8n8.x4.shared.b16 {%0,%1,%2,%3}, [%4];"
                 : "=r"(r[0]), "=r"(r[1]), "=r"(r[2]), "=r"(r[3]) : "r"(addr));
}
__device__ __forceinline__ void mma16816(float* c, const uint32_t* a, uint32_t b0, uint32_t b1) {
    asm volatile(
        "mma.sync.aligned.m16n8k16.row.col.f32.f16.f16.f32 "
        "{%0,%1,%2,%3}, {%4,%5,%6,%7}, {%8,%9}, {%0,%1,%2,%3};"
        : "+f"(c[0]), "+f"(c[1]), "+f"(c[2]), "+f"(c[3])
        : "r"(a[0]), "r"(a[1]), "r"(a[2]), "r"(a[3]), "r"(b0), "r"(b1));
}
__device__ __forceinline__ void split_write(fp16* hi, fp16* lo, size_t off, float x) {
    fp16 h = __float2half_rn(x);
    hi[off] = h;
    lo[off] = __float2half_rn(x - __half2float(h));
}

// ---------------- fp16 split GEMM: BM=BN=128, BK=32, 256 thr, 2 CTA/SM ----------
// NTERMS=3: A(hi,lo) x W(hi,lo), 2-stage (40KB/stage).
// NTERMS=2: A(hi,lo) x W single,  3-stage (30KB/stage).
// NTERMS=1: A single  x W single, 4-stage (20KB/stage).
// OUTMODE: 2 = relu + fp16; 3 = zr epilogue; 4 = n/final + fused predict; 5 = fp32+bias.
template <int OUTMODE, int NTERMS>
__global__ void __launch_bounds__(256, 2) mma3(
    const fp16* __restrict__ A1h, const fp16* __restrict__ A1l, int lda1,
    const fp16* __restrict__ A2h, const fp16* __restrict__ A2l, int lda2, int splitK,
    const fp16* __restrict__ Wh, const fp16* __restrict__ Wl, int ldw, int K,
    fp16* __restrict__ Cout, int ldc, int coff,
    const float* __restrict__ bg, const float* __restrict__ prevp,
    float* __restrict__ zbuf,
    fp16* __restrict__ rhout,
    float* __restrict__ outh,
    const float* __restrict__ Wp, float* __restrict__ predout)
{
    constexpr uint32_t ST = (NTERMS == 3) ? 40960u : (NTERMS == 2 ? 30720u : 20480u);
    constexpr int STAGES = (NTERMS == 3) ? 2 : (NTERMS == 2 ? 3 : 4);
    constexpr uint32_t WOFF = (NTERMS == 1) ? 10240u : 20480u;
    extern __shared__ char sm[];
    const uint32_t base = smem_u32(sm);
    const int t = threadIdx.x, wid = t >> 5, lane = t & 31;
    const int wm = wid & 1, wn = wid >> 1;
    const int row0 = blockIdx.y * 128, col0 = blockIdx.x * 128;
    const int chunks = K >> 5;

    auto load_stage = [&](int s, int ck) {
        int k0 = ck * 32;
        const fp16 *ah, *al;
        int lda, kk;
        if (k0 < splitK) { ah = A1h; al = A1l; lda = lda1; kk = k0; }
        else             { ah = A2h; al = A2l; lda = lda2; kk = k0 - splitK; }
        uint32_t sb = base + (uint32_t)s * ST;
#pragma unroll
        for (int half = 0; half < 2; half++) {
            int idx = t + half * 256;
            int r = idx >> 2, c = idx & 3;
            uint32_t so = r * 80 + c * 16;
            cp_async16(sb + so, ah + (size_t)(row0 + r) * lda + kk + c * 8);
            if (NTERMS >= 2)
                cp_async16(sb + 10240 + so, al + (size_t)(row0 + r) * lda + kk + c * 8);
            cp_async16(sb + WOFF + so, Wh + (size_t)(col0 + r) * ldw + k0 + c * 8);
            if (NTERMS == 3)
                cp_async16(sb + 30720 + so, Wl + (size_t)(col0 + r) * ldw + k0 + c * 8);
        }
        cp_commit();
    };

    float acc[4][4][4];
#pragma unroll
    for (int a = 0; a < 4; a++)
#pragma unroll
        for (int b = 0; b < 4; b++)
#pragma unroll
            for (int c = 0; c < 4; c++) acc[a][b][c] = 0.f;

    int issued = 0;
    for (; issued < STAGES - 1 && issued < chunks; issued++)
        load_stage(issued % STAGES, issued);

    for (int i = 0; i < chunks; i++) {
        if (issued < chunks) { load_stage(issued % STAGES, issued); issued++; }
        int pend = chunks - 1 - i;
        if (pend > STAGES - 1) pend = STAGES - 1;
        if (pend == 0)      asm volatile("cp.async.wait_group 0;" ::: "memory");
        else if (pend == 1) asm volatile("cp.async.wait_group 1;" ::: "memory");
        else if (pend == 2) asm volatile("cp.async.wait_group 2;" ::: "memory");
        else                asm volatile("cp.async.wait_group 3;" ::: "memory");
        __syncthreads();

        uint32_t sb = base + (uint32_t)(i % STAGES) * ST;
#pragma unroll
        for (int ks = 0; ks < 2; ks++) {
            int kb = ks * 16;
            int arow[4];
            int akc = (kb >> 3) + (lane >> 4);
            uint32_t ra[4][4], rbh[2][4];
#pragma unroll
            for (int im = 0; im < 4; im++) {
                arow[im] = wm * 64 + im * 16 + (lane & 15);
                ldmx4(ra[im], sb + arow[im] * 80 + akc * 16);
            }
#pragma unroll
            for (int ib = 0; ib < 2; ib++) {
                int n = wn * 32 + ib * 16 + ((lane & 16) ? 8 : 0) + (lane & 7);
                int kc = (kb >> 3) + ((lane >> 3) & 1);
                ldmx4(rbh[ib], sb + WOFF + n * 80 + kc * 16);
            }
#pragma unroll
            for (int im = 0; im < 4; im++)
#pragma unroll
                for (int in = 0; in < 4; in++)
                    mma16816(acc[im][in], ra[im], rbh[in >> 1][(in & 1) * 2], rbh[in >> 1][(in & 1) * 2 + 1]);
            if (NTERMS == 3) {
                uint32_t rbl[2][4];
#pragma unroll
                for (int ib = 0; ib < 2; ib++) {
                    int n = wn * 32 + ib * 16 + ((lane & 16) ? 8 : 0) + (lane & 7);
                    int kc = (kb >> 3) + ((lane >> 3) & 1);
                    ldmx4(rbl[ib], sb + 30720 + n * 80 + kc * 16);
                }
#pragma unroll
                for (int im = 0; im < 4; im++)
#pragma unroll
                    for (int in = 0; in < 4; in++)
                        mma16816(acc[im][in], ra[im], rbl[in >> 1][(in & 1) * 2], rbl[in >> 1][(in & 1) * 2 + 1]);
            }
            if (NTERMS >= 2) {
#pragma unroll
                for (int im = 0; im < 4; im++)
                    ldmx4(ra[im], sb + 10240 + arow[im] * 80 + akc * 16);
#pragma unroll
                for (int im = 0; im < 4; im++)
#pragma unroll
                    for (int in = 0; in < 4; in++)
                        mma16816(acc[im][in], ra[im], rbh[in >> 1][(in & 1) * 2], rbh[in >> 1][(in & 1) * 2 + 1]);
            }
        }
        __syncthreads();
    }

    // ---------------- epilogue ----------------
    if (OUTMODE == 4) {
        // n-gate + hidden + fused predict head
        float* sred = (float*)sm;   // 128 rows x 5 outputs
        for (int idx = t; idx < 128 * OUTD; idx += 256) sred[idx] = 0.f;
        __syncthreads();
#pragma unroll
        for (int im = 0; im < 4; im++) {
            float pp0[OUTD], pp1[OUTD];
#pragma unroll
            for (int o = 0; o < OUTD; o++) { pp0[o] = 0.f; pp1[o] = 0.f; }
            int m = row0 + wm * 64 + im * 16 + (lane >> 2);
#pragma unroll
            for (int in = 0; in < 4; in++) {
                int c = col0 + wn * 32 + in * 8 + (lane & 3) * 2;
                float n00 = fmaxf(acc[im][in][0] + bg[512 + c], 0.f);
                float n01 = fmaxf(acc[im][in][1] + bg[512 + c + 1], 0.f);
                float n10 = fmaxf(acc[im][in][2] + bg[512 + c], 0.f);
                float n11 = fmaxf(acc[im][in][3] + bg[512 + c + 1], 0.f);
                float z00 = zbuf[(size_t)m * 256 + c], z01 = zbuf[(size_t)m * 256 + c + 1];
                float z10 = zbuf[(size_t)(m + 8) * 256 + c], z11 = zbuf[(size_t)(m + 8) * 256 + c + 1];
                float p00 = prevp[(size_t)m * 256 + c], p01 = prevp[(size_t)m * 256 + c + 1];
                float p10 = prevp[(size_t)(m + 8) * 256 + c], p11 = prevp[(size_t)(m + 8) * 256 + c + 1];
                float h00 = (1.f - z00) * n00 + z00 * p00;
                float h01 = (1.f - z01) * n01 + z01 * p01;
                float h10 = (1.f - z10) * n10 + z10 * p10;
                float h11 = (1.f - z11) * n11 + z11 * p11;
                outh[(size_t)m * 256 + c] = h00;
                outh[(size_t)m * 256 + c + 1] = h01;
                outh[(size_t)(m + 8) * 256 + c] = h10;
                outh[(size_t)(m + 8) * 256 + c + 1] = h11;
#pragma unroll
                for (int o = 0; o < OUTD; o++) {
                    float w0 = Wp[o * 256 + c], w1 = Wp[o * 256 + c + 1];
                    pp0[o] += h00 * w0 + h01 * w1;
                    pp1[o] += h10 * w0 + h11 * w1;
                }
            }
#pragma unroll
            for (int off = 1; off <= 2; off <<= 1)
#pragma unroll
                for (int o = 0; o < OUTD; o++) {
                    pp0[o] += __shfl_xor_sync(0xffffffffu, pp0[o], off);
                    pp1[o] += __shfl_xor_sync(0xffffffffu, pp1[o], off);
                }
            if ((lane & 3) == 0) {
                int r0 = wm * 64 + im * 16 + (lane >> 2);
#pragma unroll
                for (int o = 0; o < OUTD; o++) {
                    atomicAdd(&sred[r0 * OUTD + o], pp0[o]);
                    atomicAdd(&sred[(r0 + 8) * OUTD + o], pp1[o]);
                }
            }
        }
        __syncthreads();
        for (int idx = t; idx < 128 * OUTD; idx += 256)
            atomicAdd(&predout[(size_t)(row0 + idx / OUTD) * OUTD + idx % OUTD], sred[idx]);
        return;
    }

    auto emit = [&](int mm, int cc, float v) {
        if (OUTMODE == 2) {
            Cout[(size_t)mm * ldc + coff + cc] = __float2half_rn(fmaxf(v, 0.f));
        } else if (OUTMODE == 3) {
            float s = 1.f / (1.f + expf(-(v + bg[cc])));
            if (cc < 256) {
                zbuf[(size_t)mm * 256 + cc] = s;
            } else {
                int j = cc - 256;
                rhout[(size_t)mm * 256 + j] = __float2half_rn(s * prevp[(size_t)mm * 256 + j]);
            }
        } else {  // 5: fp32 + bias
            outh[(size_t)mm * 256 + cc] = v + bg[cc];
        }
    };
#pragma unroll
    for (int im = 0; im < 4; im++) {
#pragma unroll
        for (int in = 0; in < 4; in++) {
            int m = row0 + wm * 64 + im * 16 + (lane >> 2);
            int c = col0 + wn * 32 + in * 8 + (lane & 3) * 2;
            emit(m, c, acc[im][in][0]);
            emit(m, c + 1, acc[im][in][1]);
            emit(m + 8, c, acc[im][in][2]);
            emit(m + 8, c + 1, acc[im][in][3]);
        }
    }
}

// ---------------- Mt = (Wt^T @ Ws)^T split, cvec = bt @ Ws ----------------
__global__ void computeM(const float* __restrict__ Wt, const float* __restrict__ Ws,
                         const float* __restrict__ bt,
                         fp16* __restrict__ MtH, fp16* __restrict__ MtL,
                         float* __restrict__ cvec)
{
    int k = blockIdx.x, j = threadIdx.x;
    float s = 0.f;
#pragma unroll 8
    for (int a = 0; a < 64; a++) s = fmaf(Wt[a * 256 + k], Ws[a * 256 + j], s);
    split_write(MtH, MtL, (size_t)j * 256 + k, s);
    if (k == 0) {
        float c = 0.f;
#pragma unroll 8
        for (int a = 0; a < 64; a++) c = fmaf(bt[a], Ws[a * 256 + j], c);
        cvec[j] = c;
    }
}

// ---------------- attention (writes in1 hi, cols 256:512) ----------------
__global__ void __launch_bounds__(256) attn_kernel(
    const float* __restrict__ spat, const float* __restrict__ V,
    fp16* __restrict__ hi)
{
    __shared__ float sp[NE * NH];
    __shared__ float vs[NH];
    __shared__ float attn_s[NE];
    __shared__ float ws[NE];

    int n = blockIdx.x;
    int t = threadIdx.x;

    vs[t] = V[(size_t)n * NH + t];
    const float4* g = (const float4*)(spat + (size_t)n * NE * NH);
    float4* s4 = (float4*)sp;
#pragma unroll
    for (int i = 0; i < 8; i++) s4[t + i * 256] = g[t + i * 256];
    __syncthreads();

    int warp = t >> 5, lane = t & 31;
#pragma unroll
    for (int ei = 0; ei < 4; ei++) {
        int e = warp * 4 + ei;
        float s = 0.f;
#pragma unroll
        for (int i = 0; i < 8; i++)
            s = fmaf(sp[e * NH + lane + i * 32], vs[lane + i * 32], s);
#pragma unroll
        for (int o = 16; o; o >>= 1) s += __shfl_xor_sync(0xffffffffu, s, o);
        if (lane == 0) attn_s[e] = s * 4.0f;
    }
    __syncthreads();

    if (t < 32) {
        float a = attn_s[t];
        float m = a;
#pragma unroll
        for (int o = 16; o; o >>= 1) m = fmaxf(m, __shfl_xor_sync(0xffffffffu, m, o));
        float p = expf(a - m);
        float ssum = p;
#pragma unroll
        for (int o = 16; o; o >>= 1) ssum += __shfl_xor_sync(0xffffffffu, ssum, o);
        ws[t] = p / ssum;
    }
    __syncthreads();

    float acc = 0.f;
#pragma unroll
    for (int e = 0; e < NE; e++) acc = fmaf(ws[e], sp[e * NH + t], acc);
    hi[(size_t)n * 512 + 256 + t] = __float2half_rn(acc);
}

// ---------------- fused prep: prev fp16, th split, x_e, pred-bias init ----------
__global__ void __launch_bounds__(256) prep_kernel(
    const float* __restrict__ prev, const float* __restrict__ th,
    const float* __restrict__ xy, const float* __restrict__ Wxy,
    const float* __restrict__ bp,
    fp16* __restrict__ ph,
    fp16* __restrict__ i1h, fp16* __restrict__ i1l,
    fp16* __restrict__ ch, float* __restrict__ predout)
{
    int n = blockIdx.x, c = threadIdx.x;
    size_t i = (size_t)n * 256 + c;
    ph[i] = __float2half_rn(prev[i]);
    split_write(i1h, i1l, (size_t)n * 512 + c, th[i]);
    float x0 = xy[n * 2 + 0], x1 = xy[n * 2 + 1];
    float2 w = *(const float2*)&Wxy[c * 2];
    float v = fmaxf(fmaf(x0, w.x, x1 * w.y), 0.f);
    ch[(size_t)n * 512 + c] = __float2half_rn(v);
    if (c < OUTD) predout[(size_t)n * OUTD + c] = bp[c];
}

// ---------------- weight merge + convert ----------------
__global__ void merge_weights(
    const float* __restrict__ Whe, const float* __restrict__ Wih, const float* __restrict__ Whh,
    fp16* __restrict__ WheO,
    fp16* __restrict__ Uzr, fp16* __restrict__ Un)
{
    int i = blockIdx.x * 256 + threadIdx.x;
    if (i < 131072) {
        WheO[i] = __float2half_rn(Whe[i]);
    } else if (i < 131072 + 393216) {
        int q = i - 131072;
        int j = q / 768, k = q - j * 768;
        int g = j >> 8, r = j & 255;
        float x = (k < 512) ? Wih[g * 131072 + r * 512 + k] : Whh[g * 65536 + r * 256 + (k - 512)];
        Uzr[q] = __float2half_rn(x);
    } else {
        int q = i - 524288;
        int j = q / 768, k = q - j * 768;
        float x = (k < 512) ? Wih[262144 + j * 512 + k] : Whh[131072 + j * 256 + (k - 512)];
        Un[q] = __float2half_rn(x);
    }
}

// ---------------- host launcher ----------------
extern "C" void kernel_launch(void* const* d_in, const int* in_sizes, int n_in,
                              void* d_out, int out_size)
{
    const float* xy   = (const float*)d_in[0];
    const float* th   = (const float*)d_in[1];
    const float* spat = (const float*)d_in[2];
    const float* prev = (const float*)d_in[3];
    const float* Wt   = (const float*)d_in[4];
    const float* bt   = (const float*)d_in[5];
    const float* Ws   = (const float*)d_in[6];
    // d_in[7] = bs: softmax-invariant, dropped.
    const float* Wxy  = (const float*)d_in[8];
    const float* Whe  = (const float*)d_in[9];
    const float* Wih  = (const float*)d_in[10];
    const float* Whh  = (const float*)d_in[11];
    const float* bg   = (const float*)d_in[12];
    const float* Wp   = (const float*)d_in[13];
    const float* bp   = (const float*)d_in[14];

    float* out_pred   = (float*)d_out;
    float* out_hidden = (float*)d_out + NN * OUTD;

    float *pCvec, *pV, *pZ;
    fp16 *pMth, *pMtl, *pIn1h, *pIn1l, *pCat, *pPrev, *pRh;
    fp16 *pWhe, *pUzr, *pUn;
    cudaGetSymbolAddress((void**)&pCvec, g_cvec);
    cudaGetSymbolAddress((void**)&pV, g_V);
    cudaGetSymbolAddress((void**)&pZ, g_z);
    cudaGetSymbolAddress((void**)&pMth, g_Mt_hi);
    cudaGetSymbolAddress((void**)&pMtl, g_Mt_lo);
    cudaGetSymbolAddress((void**)&pIn1h, g_in1_hi);
    cudaGetSymbolAddress((void**)&pIn1l, g_in1_lo);
    cudaGetSymbolAddress((void**)&pCat, g_cat);
    cudaGetSymbolAddress((void**)&pPrev, g_prev);
    cudaGetSymbolAddress((void**)&pRh, g_rh);
    cudaGetSymbolAddress((void**)&pWhe, g_Whe);
    cudaGetSymbolAddress((void**)&pUzr, g_Uzr);
    cudaGetSymbolAddress((void**)&pUn, g_Un);

    const int SM3 = 2 * 40960;   // 3-term, 2-stage
    const int SM1 = 4 * 20480;   // 1-term, 4-stage
    cudaFuncSetAttribute((const void*)mma3<5, 3>, cudaFuncAttributeMaxDynamicSharedMemorySize, SM3);
    cudaFuncSetAttribute((const void*)mma3<2, 1>, cudaFuncAttributeMaxDynamicSharedMemorySize, SM1);
    cudaFuncSetAttribute((const void*)mma3<3, 1>, cudaFuncAttributeMaxDynamicSharedMemorySize, SM1);
    cudaFuncSetAttribute((const void*)mma3<4, 1>, cudaFuncAttributeMaxDynamicSharedMemorySize, SM1);

    dim3 blk(256);
    const int MB = NN / 128;

    // prep
    merge_weights<<<2816, blk>>>(Whe, Wih, Whh, pWhe, pUzr, pUn);
    computeM<<<256, blk>>>(Wt, Ws, bt, pMth, pMtl, pCvec);
    prep_kernel<<<NN, blk>>>(prev, th, xy, Wxy, bp, pPrev, pIn1h, pIn1l, pCat, out_pred);

    // V = th @ Mt^T + cvec (3-term, fp32 out)
    mma3<5, 3><<<dim3(2, MB), blk, SM3>>>(
        pIn1h, pIn1l, 512, pIn1h, pIn1l, 512, 1024,
        pMth, pMtl, 256, 256,
        nullptr, 0, 0, pCvec, nullptr, nullptr, nullptr, pV, nullptr, nullptr);

    // attention -> Hagg (in1 hi, cols 256:512)
    attn_kernel<<<NN, blk>>>(spat, pV, pIn1h);

    // H_e = relu(in1 @ Whe^T) -> cat[:,256:512]  (1-term)
    mma3<2, 1><<<dim3(2, MB), blk, SM1>>>(
        pIn1h, nullptr, 512, pIn1h, nullptr, 512, 512,
        pWhe, nullptr, 512, 512,
        pCat, 512, 256, nullptr, nullptr, nullptr, nullptr, nullptr, nullptr, nullptr);

    // z,r = sigmoid([cat||prev] @ Uzr^T + bg)  (1-term); writes g_z and rh=r*prev
    mma3<3, 1><<<dim3(4, MB), blk, SM1>>>(
        pCat, nullptr, 512, pPrev, nullptr, 256, 512,
        pUzr, nullptr, 768, 768,
        nullptr, 0, 0, bg, prev, pZ, pRh, nullptr, nullptr, nullptr);

    // n GEMM + hidden + fused predict  (1-term)
    mma3<4, 1><<<dim3(2, MB), blk, SM1>>>(
        pCat, nullptr, 512, pRh, nullptr, 256, 512,
        pUn, nullptr, 768, 768,
        nullptr, 0, 0, bg, prev, pZ, nullptr, out_hidden, Wp, out_pred);
}

// round 12
// speedup vs baseline: 1.5894x; 1.0319x over previous
#include <cuda_runtime.h>
#include <cuda_fp16.h>
#include <math.h>
#include <stdint.h>

#define NN 16384
#define NE 32
#define NH 256
#define OUTD 5

typedef __half fp16;

// ---------------- scratch (device globals) ----------------
__device__ __align__(16) float g_cvec[256];
__device__ __align__(16) float g_V[NN * NH];
__device__ __align__(16) float g_z[NN * NH];

__device__ __align__(16) fp16 g_Mt_hi[256 * 256], g_Mt_lo[256 * 256];
__device__ __align__(16) fp16 g_in1_hi[NN * 512], g_in1_lo[NN * 512];  // [th || Hagg]
__device__ __align__(16) fp16 g_cat[NN * 512];                          // [x_e || H_e]
__device__ __align__(16) fp16 g_prev[NN * 256];
__device__ __align__(16) fp16 g_rh[NN * 256];
__device__ __align__(16) fp16 g_Whe[256 * 512];
__device__ __align__(16) fp16 g_Uzr[512 * 768];
__device__ __align__(16) fp16 g_Un[256 * 768];

// ---------------- PTX helpers ----------------
__device__ __forceinline__ uint32_t smem_u32(const void* p) {
    uint32_t a;
    asm("{ .reg .u64 t; cvta.to.shared.u64 t, %1; cvt.u32.u64 %0, t; }" : "=r"(a) : "l"(p));
    return a;
}
__device__ __forceinline__ void cp_async16(uint32_t s, const void* g) {
    asm volatile("cp.async.cg.shared.global [%0], [%1], 16;" :: "r"(s), "l"(g) : "memory");
}
__device__ __forceinline__ void cp_commit() {
    asm volatile("cp.async.commit_group;" ::: "memory");
}
__device__ __forceinline__ void ldmx4(uint32_t* r, uint32_t addr) {
    asm volatile("ldmatrix.sync.aligned.m8n8.x4.shared.b16 {%0,%1,%2,%3}, [%4];"
                 : "=r"(r[0]), "=r"(r[1]), "=r"(r[2]), "=r"(r[3]) : "r"(addr));
}
__device__ __forceinline__ void mma16816(float* c, const uint32_t* a, uint32_t b0, uint32_t b1) {
    asm volatile(
        "mma.sync.aligned.m16n8k16.row.col.f32.f16.f16.f32 "
        "{%0,%1,%2,%3}, {%4,%5,%6,%7}, {%8,%9}, {%0,%1,%2,%3};"
        : "+f"(c[0]), "+f"(c[1]), "+f"(c[2]), "+f"(c[3])
        : "r"(a[0]), "r"(a[1]), "r"(a[2]), "r"(a[3]), "r"(b0), "r"(b1));
}
__device__ __forceinline__ void split_write(fp16* hi, fp16* lo, size_t off, float x) {
    fp16 h = __float2half_rn(x);
    hi[off] = h;
    lo[off] = __float2half_rn(x - __half2float(h));
}

// ---------------- fp16 split GEMM: BM=BN=128, 256 thr, 2 CTA/SM ----------
// NTERMS=3: BK=32, A(hi,lo) x W(hi,lo), 2-stage (40KB/stage), pitch 80.
// NTERMS=1: BK=64, A x W single, 3-stage (36.9KB/stage), pitch 144.
// OUTMODE: 2 = relu + fp16; 3 = zr epilogue; 4 = n/final + fused predict; 5 = fp32+bias.
template <int OUTMODE, int NTERMS>
__global__ void __launch_bounds__(256, 2) mma3(
    const fp16* __restrict__ A1h, const fp16* __restrict__ A1l, int lda1,
    const fp16* __restrict__ A2h, const fp16* __restrict__ A2l, int lda2, int splitK,
    const fp16* __restrict__ Wh, const fp16* __restrict__ Wl, int ldw, int K,
    fp16* __restrict__ Cout, int ldc, int coff,
    const float* __restrict__ bg, const float* __restrict__ prevp,
    float* __restrict__ zbuf,
    fp16* __restrict__ rhout,
    float* __restrict__ outh,
    const float* __restrict__ Wp, float* __restrict__ predout)
{
    constexpr int BK = (NTERMS == 1) ? 64 : 32;
    constexpr uint32_t PITCH = (NTERMS == 1) ? 144u : 80u;
    constexpr uint32_t TILE = 128u * PITCH;                 // bytes per tile
    constexpr uint32_t ST = (NTERMS == 3) ? 4 * TILE : TILE * 2;  // 3-term: 4 tiles; 1-term: 2 tiles
    constexpr int STAGES = (NTERMS == 3) ? 2 : 3;
    constexpr int CPR = BK / 8;                             // 16B chunks per row
    constexpr uint32_t WOFF = (NTERMS == 1) ? TILE : 2 * TILE;  // W-hi tile offset
    extern __shared__ char sm[];
    const uint32_t base = smem_u32(sm);
    const int t = threadIdx.x, wid = t >> 5, lane = t & 31;
    const int wm = wid & 1, wn = wid >> 1;
    const int row0 = blockIdx.y * 128, col0 = blockIdx.x * 128;
    const int chunks = K / BK;

    auto load_stage = [&](int s, int ck) {
        int k0 = ck * BK;
        const fp16 *ah, *al;
        int lda, kk;
        if (k0 < splitK) { ah = A1h; al = A1l; lda = lda1; kk = k0; }
        else             { ah = A2h; al = A2l; lda = lda2; kk = k0 - splitK; }
        uint32_t sb = base + (uint32_t)s * ST;
#pragma unroll
        for (int i = 0; i < 128 * CPR / 256; i++) {
            int idx = t + i * 256;
            int r = idx / CPR, c = idx % CPR;
            uint32_t so = r * PITCH + c * 16;
            cp_async16(sb + so, ah + (size_t)(row0 + r) * lda + kk + c * 8);
            if (NTERMS >= 2)
                cp_async16(sb + TILE + so, al + (size_t)(row0 + r) * lda + kk + c * 8);
            cp_async16(sb + WOFF + so, Wh + (size_t)(col0 + r) * ldw + k0 + c * 8);
            if (NTERMS == 3)
                cp_async16(sb + 3 * TILE + so, Wl + (size_t)(col0 + r) * ldw + k0 + c * 8);
        }
        cp_commit();
    };

    float acc[4][4][4];
#pragma unroll
    for (int a = 0; a < 4; a++)
#pragma unroll
        for (int b = 0; b < 4; b++)
#pragma unroll
            for (int c = 0; c < 4; c++) acc[a][b][c] = 0.f;

    int issued = 0;
    for (; issued < STAGES - 1 && issued < chunks; issued++)
        load_stage(issued % STAGES, issued);

    for (int i = 0; i < chunks; i++) {
        if (issued < chunks) { load_stage(issued % STAGES, issued); issued++; }
        int pend = chunks - 1 - i;
        if (pend > STAGES - 1) pend = STAGES - 1;
        if (pend == 0)      asm volatile("cp.async.wait_group 0;" ::: "memory");
        else if (pend == 1) asm volatile("cp.async.wait_group 1;" ::: "memory");
        else                asm volatile("cp.async.wait_group 2;" ::: "memory");
        __syncthreads();

        uint32_t sb = base + (uint32_t)(i % STAGES) * ST;
#pragma unroll
        for (int ks = 0; ks < BK / 16; ks++) {
            int arow[4];
            int akc = ks * 2 + (lane >> 4);
            uint32_t ra[4][4], rbh[2][4];
#pragma unroll
            for (int im = 0; im < 4; im++) {
                arow[im] = wm * 64 + im * 16 + (lane & 15);
                ldmx4(ra[im], sb + arow[im] * PITCH + akc * 16);
            }
#pragma unroll
            for (int ib = 0; ib < 2; ib++) {
                int n = wn * 32 + ib * 16 + ((lane & 16) ? 8 : 0) + (lane & 7);
                int kc = ks * 2 + ((lane >> 3) & 1);
                ldmx4(rbh[ib], sb + WOFF + n * PITCH + kc * 16);
            }
#pragma unroll
            for (int im = 0; im < 4; im++)
#pragma unroll
                for (int in = 0; in < 4; in++)
                    mma16816(acc[im][in], ra[im], rbh[in >> 1][(in & 1) * 2], rbh[in >> 1][(in & 1) * 2 + 1]);
            if (NTERMS == 3) {
                uint32_t rbl[2][4];
#pragma unroll
                for (int ib = 0; ib < 2; ib++) {
                    int n = wn * 32 + ib * 16 + ((lane & 16) ? 8 : 0) + (lane & 7);
                    int kc = ks * 2 + ((lane >> 3) & 1);
                    ldmx4(rbl[ib], sb + 3 * TILE + n * PITCH + kc * 16);
                }
#pragma unroll
                for (int im = 0; im < 4; im++)
#pragma unroll
                    for (int in = 0; in < 4; in++)
                        mma16816(acc[im][in], ra[im], rbl[in >> 1][(in & 1) * 2], rbl[in >> 1][(in & 1) * 2 + 1]);
            }
            if (NTERMS >= 2) {
#pragma unroll
                for (int im = 0; im < 4; im++)
                    ldmx4(ra[im], sb + TILE + arow[im] * PITCH + akc * 16);
#pragma unroll
                for (int im = 0; im < 4; im++)
#pragma unroll
                    for (int in = 0; in < 4; in++)
                        mma16816(acc[im][in], ra[im], rbh[in >> 1][(in & 1) * 2], rbh[in >> 1][(in & 1) * 2 + 1]);
            }
        }
        __syncthreads();
    }

    // ---------------- epilogue ----------------
    if (OUTMODE == 4) {
        // n-gate + hidden + fused predict head
        float* sred = (float*)sm;   // 128 rows x 5 outputs
        for (int idx = t; idx < 128 * OUTD; idx += 256) sred[idx] = 0.f;
        __syncthreads();
#pragma unroll
        for (int im = 0; im < 4; im++) {
            float pp0[OUTD], pp1[OUTD];
#pragma unroll
            for (int o = 0; o < OUTD; o++) { pp0[o] = 0.f; pp1[o] = 0.f; }
            int m = row0 + wm * 64 + im * 16 + (lane >> 2);
#pragma unroll
            for (int in = 0; in < 4; in++) {
                int c = col0 + wn * 32 + in * 8 + (lane & 3) * 2;
                float n00 = fmaxf(acc[im][in][0] + bg[512 + c], 0.f);
                float n01 = fmaxf(acc[im][in][1] + bg[512 + c + 1], 0.f);
                float n10 = fmaxf(acc[im][in][2] + bg[512 + c], 0.f);
                float n11 = fmaxf(acc[im][in][3] + bg[512 + c + 1], 0.f);
                float z00 = zbuf[(size_t)m * 256 + c], z01 = zbuf[(size_t)m * 256 + c + 1];
                float z10 = zbuf[(size_t)(m + 8) * 256 + c], z11 = zbuf[(size_t)(m + 8) * 256 + c + 1];
                float p00 = prevp[(size_t)m * 256 + c], p01 = prevp[(size_t)m * 256 + c + 1];
                float p10 = prevp[(size_t)(m + 8) * 256 + c], p11 = prevp[(size_t)(m + 8) * 256 + c + 1];
                float h00 = (1.f - z00) * n00 + z00 * p00;
                float h01 = (1.f - z01) * n01 + z01 * p01;
                float h10 = (1.f - z10) * n10 + z10 * p10;
                float h11 = (1.f - z11) * n11 + z11 * p11;
                outh[(size_t)m * 256 + c] = h00;
                outh[(size_t)m * 256 + c + 1] = h01;
                outh[(size_t)(m + 8) * 256 + c] = h10;
                outh[(size_t)(m + 8) * 256 + c + 1] = h11;
#pragma unroll
                for (int o = 0; o < OUTD; o++) {
                    float w0 = Wp[o * 256 + c], w1 = Wp[o * 256 + c + 1];
                    pp0[o] += h00 * w0 + h01 * w1;
                    pp1[o] += h10 * w0 + h11 * w1;
                }
            }
#pragma unroll
            for (int off = 1; off <= 2; off <<= 1)
#pragma unroll
                for (int o = 0; o < OUTD; o++) {
                    pp0[o] += __shfl_xor_sync(0xffffffffu, pp0[o], off);
                    pp1[o] += __shfl_xor_sync(0xffffffffu, pp1[o], off);
                }
            if ((lane & 3) == 0) {
                int r0 = wm * 64 + im * 16 + (lane >> 2);
#pragma unroll
                for (int o = 0; o < OUTD; o++) {
                    atomicAdd(&sred[r0 * OUTD + o], pp0[o]);
                    atomicAdd(&sred[(r0 + 8) * OUTD + o], pp1[o]);
                }
            }
        }
        __syncthreads();
        for (int idx = t; idx < 128 * OUTD; idx += 256)
            atomicAdd(&predout[(size_t)(row0 + idx / OUTD) * OUTD + idx % OUTD], sred[idx]);
        return;
    }

    auto emit = [&](int mm, int cc, float v) {
        if (OUTMODE == 2) {
            Cout[(size_t)mm * ldc + coff + cc] = __float2half_rn(fmaxf(v, 0.f));
        } else if (OUTMODE == 3) {
            float s = 1.f / (1.f + expf(-(v + bg[cc])));
            if (cc < 256) {
                zbuf[(size_t)mm * 256 + cc] = s;
            } else {
                int j = cc - 256;
                rhout[(size_t)mm * 256 + j] = __float2half_rn(s * prevp[(size_t)mm * 256 + j]);
            }
        } else {  // 5: fp32 + bias
            outh[(size_t)mm * 256 + cc] = v + bg[cc];
        }
    };
#pragma unroll
    for (int im = 0; im < 4; im++) {
#pragma unroll
        for (int in = 0; in < 4; in++) {
            int m = row0 + wm * 64 + im * 16 + (lane >> 2);
            int c = col0 + wn * 32 + in * 8 + (lane & 3) * 2;
            emit(m, c, acc[im][in][0]);
            emit(m, c + 1, acc[im][in][1]);
            emit(m + 8, c, acc[im][in][2]);
            emit(m + 8, c + 1, acc[im][in][3]);
        }
    }
}

// ---------------- Mt = (Wt^T @ Ws)^T split, cvec = bt @ Ws ----------------
__global__ void computeM(const float* __restrict__ Wt, const float* __restrict__ Ws,
                         const float* __restrict__ bt,
                         fp16* __restrict__ MtH, fp16* __restrict__ MtL,
                         float* __restrict__ cvec)
{
    int k = blockIdx.x, j = threadIdx.x;
    float s = 0.f;
#pragma unroll 8
    for (int a = 0; a < 64; a++) s = fmaf(Wt[a * 256 + k], Ws[a * 256 + j], s);
    split_write(MtH, MtL, (size_t)j * 256 + k, s);
    if (k == 0) {
        float c = 0.f;
#pragma unroll 8
        for (int a = 0; a < 64; a++) c = fmaf(bt[a], Ws[a * 256 + j], c);
        cvec[j] = c;
    }
}

// ---------------- attention (writes in1 hi, cols 256:512) ----------------
__global__ void __launch_bounds__(256) attn_kernel(
    const float* __restrict__ spat, const float* __restrict__ V,
    fp16* __restrict__ hi)
{
    __shared__ float sp[NE * NH];
    __shared__ float vs[NH];
    __shared__ float attn_s[NE];
    __shared__ float ws[NE];

    int n = blockIdx.x;
    int t = threadIdx.x;

    vs[t] = V[(size_t)n * NH + t];
    const float4* g = (const float4*)(spat + (size_t)n * NE * NH);
    float4* s4 = (float4*)sp;
#pragma unroll
    for (int i = 0; i < 8; i++) s4[t + i * 256] = g[t + i * 256];
    __syncthreads();

    int warp = t >> 5, lane = t & 31;
#pragma unroll
    for (int ei = 0; ei < 4; ei++) {
        int e = warp * 4 + ei;
        float s = 0.f;
#pragma unroll
        for (int i = 0; i < 8; i++)
            s = fmaf(sp[e * NH + lane + i * 32], vs[lane + i * 32], s);
#pragma unroll
        for (int o = 16; o; o >>= 1) s += __shfl_xor_sync(0xffffffffu, s, o);
        if (lane == 0) attn_s[e] = s * 4.0f;
    }
    __syncthreads();

    if (t < 32) {
        float a = attn_s[t];
        float m = a;
#pragma unroll
        for (int o = 16; o; o >>= 1) m = fmaxf(m, __shfl_xor_sync(0xffffffffu, m, o));
        float p = expf(a - m);
        float ssum = p;
#pragma unroll
        for (int o = 16; o; o >>= 1) ssum += __shfl_xor_sync(0xffffffffu, ssum, o);
        ws[t] = p / ssum;
    }
    __syncthreads();

    float acc = 0.f;
#pragma unroll
    for (int e = 0; e < NE; e++) acc = fmaf(ws[e], sp[e * NH + t], acc);
    hi[(size_t)n * 512 + 256 + t] = __float2half_rn(acc);
}

// ---------------- fused prep: prev fp16, th split, x_e, pred-bias init ----------
__global__ void __launch_bounds__(256) prep_kernel(
    const float* __restrict__ prev, const float* __restrict__ th,
    const float* __restrict__ xy, const float* __restrict__ Wxy,
    const float* __restrict__ bp,
    fp16* __restrict__ ph,
    fp16* __restrict__ i1h, fp16* __restrict__ i1l,
    fp16* __restrict__ ch, float* __restrict__ predout)
{
    int n = blockIdx.x, c = threadIdx.x;
    size_t i = (size_t)n * 256 + c;
    ph[i] = __float2half_rn(prev[i]);
    split_write(i1h, i1l, (size_t)n * 512 + c, th[i]);
    float x0 = xy[n * 2 + 0], x1 = xy[n * 2 + 1];
    float2 w = *(const float2*)&Wxy[c * 2];
    float v = fmaxf(fmaf(x0, w.x, x1 * w.y), 0.f);
    ch[(size_t)n * 512 + c] = __float2half_rn(v);
    if (c < OUTD) predout[(size_t)n * OUTD + c] = bp[c];
}

// ---------------- weight merge + convert ----------------
__global__ void merge_weights(
    const float* __restrict__ Whe, const float* __restrict__ Wih, const float* __restrict__ Whh,
    fp16* __restrict__ WheO,
    fp16* __restrict__ Uzr, fp16* __restrict__ Un)
{
    int i = blockIdx.x * 256 + threadIdx.x;
    if (i < 131072) {
        WheO[i] = __float2half_rn(Whe[i]);
    } else if (i < 131072 + 393216) {
        int q = i - 131072;
        int j = q / 768, k = q - j * 768;
        int g = j >> 8, r = j & 255;
        float x = (k < 512) ? Wih[g * 131072 + r * 512 + k] : Whh[g * 65536 + r * 256 + (k - 512)];
        Uzr[q] = __float2half_rn(x);
    } else {
        int q = i - 524288;
        int j = q / 768, k = q - j * 768;
        float x = (k < 512) ? Wih[262144 + j * 512 + k] : Whh[131072 + j * 256 + (k - 512)];
        Un[q] = __float2half_rn(x);
    }
}

// ---------------- host launcher ----------------
extern "C" void kernel_launch(void* const* d_in, const int* in_sizes, int n_in,
                              void* d_out, int out_size)
{
    const float* xy   = (const float*)d_in[0];
    const float* th   = (const float*)d_in[1];
    const float* spat = (const float*)d_in[2];
    const float* prev = (const float*)d_in[3];
    const float* Wt   = (const float*)d_in[4];
    const float* bt   = (const float*)d_in[5];
    const float* Ws   = (const float*)d_in[6];
    // d_in[7] = bs: softmax-invariant, dropped.
    const float* Wxy  = (const float*)d_in[8];
    const float* Whe  = (const float*)d_in[9];
    const float* Wih  = (const float*)d_in[10];
    const float* Whh  = (const float*)d_in[11];
    const float* bg   = (const float*)d_in[12];
    const float* Wp   = (const float*)d_in[13];
    const float* bp   = (const float*)d_in[14];

    float* out_pred   = (float*)d_out;
    float* out_hidden = (float*)d_out + NN * OUTD;

    float *pCvec, *pV, *pZ;
    fp16 *pMth, *pMtl, *pIn1h, *pIn1l, *pCat, *pPrev, *pRh;
    fp16 *pWhe, *pUzr, *pUn;
    cudaGetSymbolAddress((void**)&pCvec, g_cvec);
    cudaGetSymbolAddress((void**)&pV, g_V);
    cudaGetSymbolAddress((void**)&pZ, g_z);
    cudaGetSymbolAddress((void**)&pMth, g_Mt_hi);
    cudaGetSymbolAddress((void**)&pMtl, g_Mt_lo);
    cudaGetSymbolAddress((void**)&pIn1h, g_in1_hi);
    cudaGetSymbolAddress((void**)&pIn1l, g_in1_lo);
    cudaGetSymbolAddress((void**)&pCat, g_cat);
    cudaGetSymbolAddress((void**)&pPrev, g_prev);
    cudaGetSymbolAddress((void**)&pRh, g_rh);
    cudaGetSymbolAddress((void**)&pWhe, g_Whe);
    cudaGetSymbolAddress((void**)&pUzr, g_Uzr);
    cudaGetSymbolAddress((void**)&pUn, g_Un);

    const int SM3 = 2 * 4 * (128 * 80);    // 3-term BK32: 2 stages x 40960
    const int SM1 = 3 * 2 * (128 * 144);   // 1-term BK64: 3 stages x 36864
    cudaFuncSetAttribute((const void*)mma3<5, 3>, cudaFuncAttributeMaxDynamicSharedMemorySize, SM3);
    cudaFuncSetAttribute((const void*)mma3<2, 1>, cudaFuncAttributeMaxDynamicSharedMemorySize, SM1);
    cudaFuncSetAttribute((const void*)mma3<3, 1>, cudaFuncAttributeMaxDynamicSharedMemorySize, SM1);
    cudaFuncSetAttribute((const void*)mma3<4, 1>, cudaFuncAttributeMaxDynamicSharedMemorySize, SM1);

    dim3 blk(256);
    const int MB = NN / 128;

    // prep
    merge_weights<<<2816, blk>>>(Whe, Wih, Whh, pWhe, pUzr, pUn);
    computeM<<<256, blk>>>(Wt, Ws, bt, pMth, pMtl, pCvec);
    prep_kernel<<<NN, blk>>>(prev, th, xy, Wxy, bp, pPrev, pIn1h, pIn1l, pCat, out_pred);

    // V = th @ Mt^T + cvec (3-term, fp32 out)
    mma3<5, 3><<<dim3(2, MB), blk, SM3>>>(
        pIn1h, pIn1l, 512, pIn1h, pIn1l, 512, 1024,
        pMth, pMtl, 256, 256,
        nullptr, 0, 0, pCvec, nullptr, nullptr, nullptr, pV, nullptr, nullptr);

    // attention -> Hagg (in1 hi, cols 256:512)
    attn_kernel<<<NN, blk>>>(spat, pV, pIn1h);

    // H_e = relu(in1 @ Whe^T) -> cat[:,256:512]  (1-term, BK64)
    mma3<2, 1><<<dim3(2, MB), blk, SM1>>>(
        pIn1h, nullptr, 512, pIn1h, nullptr, 512, 512,
        pWhe, nullptr, 512, 512,
        pCat, 512, 256, nullptr, nullptr, nullptr, nullptr, nullptr, nullptr, nullptr);

    // z,r = sigmoid([cat||prev] @ Uzr^T + bg)  (1-term, BK64); writes g_z and rh=r*prev
    mma3<3, 1><<<dim3(4, MB), blk, SM1>>>(
        pCat, nullptr, 512, pPrev, nullptr, 256, 512,
        pUzr, nullptr, 768, 768,
        nullptr, 0, 0, bg, prev, pZ, pRh, nullptr, nullptr, nullptr);

    // n GEMM + hidden + fused predict  (1-term, BK64)
    mma3<4, 1><<<dim3(2, MB), blk, SM1>>>(
        pCat, nullptr, 512, pRh, nullptr, 256, 512,
        pUn, nullptr, 768, 768,
        nullptr, 0, 0, bg, prev, pZ, nullptr, out_hidden, Wp, out_pred);
}